// round 5
// baseline (speedup 1.0000x reference)
#include <cuda_runtime.h>

#define NN 4096
#define FIN 128
#define FO 64
#define HH 4
#define CC 512   // 256 proj cols (h*64+o) + 256 skip cols

// ---------------- scratch (static device globals; no allocation) ----------------
__device__ float  g_emask[(size_t)NN * NN];   // exp(mask), 64 MB
__device__ float  g_hidden[(size_t)NN * CC];  // [n][c]: c<256 proj, c>=256 skip (8 MB)
__device__ float  g_Wc[FIN * CC];             // combined weights [f][c]
__device__ float4 g_A[HH * NN];               // per (h,i): a, e^a, e^{0.2a}, -
__device__ float4 g_B[HH * NN];               // per (h,j): b, e^b, e^{0.2b}, invZ

// ---------------- helpers ----------------
__device__ __forceinline__ float2 unpack2(unsigned long long v) {
    float2 r; asm("mov.b64 {%0,%1}, %2;" : "=f"(r.x), "=f"(r.y) : "l"(v)); return r;
}
__device__ __forceinline__ void fma2(unsigned long long& acc, unsigned long long a, unsigned long long b) {
    asm("fma.rn.f32x2 %0, %1, %2, %0;" : "+l"(acc) : "l"(a), "l"(b));
}
__device__ __forceinline__ float maskf(float d, float b, float cut) {
    float wdm = d + b;
    return wdm > 0.f ? wdm : (b > cut ? (b + wdm) : -1e9f);
}

// ---------------- K0: build combined weight matrix Wc[f][c] ----------------
__global__ void k0_weights(const float* __restrict__ projp, const float* __restrict__ skw) {
    int idx = blockIdx.x * 256 + threadIdx.x;   // 128*512 = 65536
    int f = idx >> 9, c = idx & 511;
    float v;
    if (c < 256) v = projp[(c >> 6) * (FIN * FO) + f * FO + (c & 63)];
    else         v = skw[(c - 256) * FIN + f];
    g_Wc[idx] = v;
}

// ---------------- K1: hidden = nodes[4096,128] @ Wc[128,512] ----------------
__global__ void __launch_bounds__(256) k1_gemm(const float* __restrict__ nodes) {
    __shared__ float sN[32 * 128];
    __shared__ float sW[128 * 64];
    const int t = threadIdx.x;
    const int i0 = blockIdx.x * 32;
    const int c0 = blockIdx.y * 64;
#pragma unroll
    for (int k = 0; k < 4; k++) {
        int q = t + k * 256;                    // 1024 float4 of node tile (contiguous)
        ((float4*)sN)[q] = ((const float4*)(nodes + (size_t)i0 * FIN))[q];
    }
#pragma unroll
    for (int k = 0; k < 8; k++) {
        int idx = t + k * 256;                  // 2048 float4 of W tile
        int f = idx >> 4, q = idx & 15;
        *(float4*)(sW + f * 64 + q * 4) = *(const float4*)(g_Wc + f * CC + c0 + q * 4);
    }
    __syncthreads();
    const int c = t & 63, rg = t >> 6;          // 64 cols x 4 row-groups (8 rows each)
    float acc[8] = {0.f,0.f,0.f,0.f,0.f,0.f,0.f,0.f};
#pragma unroll 4
    for (int f = 0; f < 128; f++) {
        float wv = sW[f * 64 + c];
#pragma unroll
        for (int r = 0; r < 8; r++)
            acc[r] += sN[(rg * 8 + r) * 128 + f] * wv;
    }
#pragma unroll
    for (int r = 0; r < 8; r++)
        g_hidden[(size_t)(i0 + rg * 8 + r) * CC + c0 + c] = acc[r];
}

// ---------------- K2: per-(h,n) scores a,b and their exponentials ----------------
__global__ void __launch_bounds__(256) k2_scores(const float* __restrict__ ssrc,
                                                 const float* __restrict__ stgt) {
    int w = blockIdx.x * 8 + (threadIdx.x >> 5);    // one warp per (h,n)
    int lane = threadIdx.x & 31;
    int h = w >> 12, n = w & (NN - 1);
    const float* pr = g_hidden + (size_t)n * CC + h * FO;
    float p0 = pr[lane], p1 = pr[lane + 32];
    float sa = p0 * ssrc[h * FO + lane] + p1 * ssrc[h * FO + lane + 32];
    float sb = p0 * stgt[h * FO + lane] + p1 * stgt[h * FO + lane + 32];
#pragma unroll
    for (int o = 16; o > 0; o >>= 1) {
        sa += __shfl_xor_sync(0xffffffffu, sa, o);
        sb += __shfl_xor_sync(0xffffffffu, sb, o);
    }
    if (lane == 0) {
        g_A[h * NN + n] = make_float4(sa, __expf(sa), __expf(0.2f * sa), 0.f);
        g_B[h * NN + n] = make_float4(sb, __expf(sb), __expf(0.2f * sb), 0.f);
    }
}

// ---------------- K3: mask -> emask + LayerNorm(mask) in one row pass ----------------
__global__ void __launch_bounds__(256) k3_mask(const float* __restrict__ deg,
                                               const float* __restrict__ bond,
                                               const float* __restrict__ cutp,
                                               float* __restrict__ out_ln) {
    __shared__ float srow[NN];
    __shared__ float red1[256], red2[256];
    const int i = blockIdx.x;
    const int t = threadIdx.x;
    const float cut = cutp[0];
    const float4* d4 = (const float4*)(deg  + (size_t)i * NN);
    const float4* b4 = (const float4*)(bond + (size_t)i * NN);
    float4* e4 = (float4*)(g_emask + (size_t)i * NN);
    float s = 0.f, sq = 0.f;
#pragma unroll
    for (int k = 0; k < 4; k++) {
        int q = t + k * 256;
        float4 dv = d4[q], bv = b4[q];
        float4 mv;
        mv.x = maskf(dv.x, bv.x, cut);
        mv.y = maskf(dv.y, bv.y, cut);
        mv.z = maskf(dv.z, bv.z, cut);
        mv.w = maskf(dv.w, bv.w, cut);
        ((float4*)srow)[q] = mv;
        e4[q] = make_float4(__expf(mv.x), __expf(mv.y), __expf(mv.z), __expf(mv.w));
        s  += (mv.x + mv.y) + (mv.z + mv.w);
        sq += mv.x * mv.x + mv.y * mv.y + mv.z * mv.z + mv.w * mv.w;
    }
    red1[t] = s; red2[t] = sq;
    __syncthreads();
    for (int o = 128; o > 0; o >>= 1) {
        if (t < o) { red1[t] += red1[t + o]; red2[t] += red2[t + o]; }
        __syncthreads();
    }
    float mu  = red1[0] * (1.f / NN);
    float var = red2[0] * (1.f / NN) - mu * mu;
    float rs  = rsqrtf(var + 1e-5f);
    float4* o4 = (float4*)(out_ln + (size_t)i * NN);
#pragma unroll
    for (int k = 0; k < 4; k++) {
        int q = t + k * 256;
        float4 mv = ((float4*)srow)[q];
        o4[q] = make_float4((mv.x - mu) * rs, (mv.y - mu) * rs,
                            (mv.z - mu) * rs, (mv.w - mu) * rs);
    }
}

// ---------------- K5: column sums -> invZ[h][j] (no atomics) ----------------
__global__ void __launch_bounds__(256) k5_colsum() {
    __shared__ float4 sA[4 * 256];
    __shared__ float sS1[4 * 8 * 32];
    __shared__ float sS2[4 * 8 * 32];
    const int t = threadIdx.x;
    const int j0 = blockIdx.x * 32;
    const int col = t & 31, seg = t >> 5;
    const int j = j0 + col;
    float thr[4];
#pragma unroll
    for (int h = 0; h < 4; h++) thr[h] = -g_B[h * NN + j].x;
    float S1[4] = {0,0,0,0}, S2[4] = {0,0,0,0};
    for (int c0 = 0; c0 < NN; c0 += 256) {
        __syncthreads();
#pragma unroll
        for (int k = 0; k < 4; k++) {
            int idx = t + k * 256;                       // 1024 = 4 heads x 256 rows
            sA[idx] = g_A[(idx >> 8) * NN + c0 + (idx & 255)];
        }
        __syncthreads();
        const float* emp = g_emask + (size_t)(c0 + seg * 32) * NN + j;
#pragma unroll 4
        for (int s = 0; s < 32; s++) {
            float em = emp[(size_t)s * NN];
#pragma unroll
            for (int h = 0; h < 4; h++) {
                float4 av = sA[h * 256 + seg * 32 + s];
                if (av.x > thr[h]) S1[h] += av.y * em; else S2[h] += av.z * em;
            }
        }
    }
#pragma unroll
    for (int h = 0; h < 4; h++) {
        sS1[(h * 8 + seg) * 32 + col] = S1[h];
        sS2[(h * 8 + seg) * 32 + col] = S2[h];
    }
    __syncthreads();
    if (t < 128) {
        int h = t >> 5, c = t & 31;
        float z1 = 0.f, z2 = 0.f;
#pragma unroll
        for (int s = 0; s < 8; s++) { z1 += sS1[(h * 8 + s) * 32 + c]; z2 += sS2[(h * 8 + s) * 32 + c]; }
        float4 Bv = g_B[h * NN + j0 + c];
        float Z = Bv.y * z1 + Bv.z * z2;
        ((float*)&g_B[h * NN + j0 + c])[3] = 1.0f / Z;
    }
}

// ---------------- K4: out = attn @ proj + skip, ELU (f32x2 FMA) ----------------
// block: head h, 32 rows; 256 threads. Per 128-wide j tile:
//   phase A: w[i][j] = sel(a_i>-b_j)? eA*eB*invZ : eA2*eB2*invZ, * emask  (stored as (w,w) float2)
//   phase B: acc(f-pair) += proj[j][f-pair] * (w,w) via fma.rn.f32x2
__global__ void __launch_bounds__(256) k4_agg(float* __restrict__ out) {
    extern __shared__ float sm[];
    float*  sProj = sm;                          // 128*64 = 8192 floats
    float2* sW2   = (float2*)(sm + 8192);        // 128 rows * stride 34 float2 = 8704 floats
    float4* sAr   = (float4*)(sm + 8192 + 8704); // 32 float4
    const int i0 = blockIdx.x * 32;
    const int h  = blockIdx.y;
    const int t  = threadIdx.x;
    const int jl = t & 127, ihalf = t >> 7;      // phase A mapping
    const int fp = t & 31,  g = t >> 5;          // phase B mapping: f-pair, row group
    if (t < 32) sAr[t] = g_A[h * NN + i0 + t];
    unsigned long long acc0 = 0ull, acc1 = 0ull, acc2 = 0ull, acc3 = 0ull;
    for (int j0 = 0; j0 < NN; j0 += 128) {
        __syncthreads();
        // stage proj tile [128][64]
#pragma unroll
        for (int k = 0; k < 8; k++) {
            int idx = t + k * 256;
            int jr = idx >> 4, q = idx & 15;
            *(float4*)(sProj + jr * 64 + q * 4) =
                *(const float4*)(g_hidden + (size_t)(j0 + jr) * CC + h * FO + q * 4);
        }
        float4 Bv = g_B[h * NN + j0 + jl];
        float thr = -Bv.x;
        float e1 = Bv.y * Bv.w;   // e^b * invZ
        float e2 = Bv.z * Bv.w;   // e^{0.2b} * invZ
        const float* emrow = g_emask + (size_t)i0 * NN + j0 + jl;
#pragma unroll
        for (int s = 0; s < 16; s++) {
            int il = ihalf * 16 + s;
            float em = emrow[(size_t)il * NN];
            float4 av = sAr[il];
            float v = (av.x > thr) ? (av.y * e1) : (av.z * e2);
            float w = v * em;
            sW2[jl * 34 + ((il & 7) * 4 + (il >> 3))] = make_float2(w, w);
        }
        __syncthreads();
#pragma unroll 8
        for (int jj = 0; jj < 128; jj++) {
            unsigned long long p = *(const unsigned long long*)(sProj + jj * 64 + fp * 2);
            ulonglong2 wa = *(const ulonglong2*)(sW2 + jj * 34 + g * 4);
            ulonglong2 wb = *(const ulonglong2*)(sW2 + jj * 34 + g * 4 + 2);
            fma2(acc0, p, wa.x);   // row g
            fma2(acc1, p, wa.y);   // row g+8
            fma2(acc2, p, wb.x);   // row g+16
            fma2(acc3, p, wb.y);   // row g+24
        }
    }
    unsigned long long accs[4] = {acc0, acc1, acc2, acc3};
#pragma unroll
    for (int k = 0; k < 4; k++) {
        int i = i0 + g + 8 * k;
        float2 a = unpack2(accs[k]);
        const float2 sk = *(const float2*)(g_hidden + (size_t)i * CC + 256 + h * FO + fp * 2);
        float x0 = a.x + sk.x, x1 = a.y + sk.y;
        x0 = x0 > 0.f ? x0 : (__expf(x0) - 1.f);
        x1 = x1 > 0.f ? x1 : (__expf(x1) - 1.f);
        *(float2*)(out + (size_t)i * 256 + h * FO + fp * 2) = make_float2(x0, x1);
    }
}

// ---------------- launcher ----------------
extern "C" void kernel_launch(void* const* d_in, const int* in_sizes, int n_in,
                              void* d_out, int out_size) {
    const float* nodes = (const float*)d_in[0];
    const float* degm  = (const float*)d_in[1];
    // d_in[2] = edges_features_distance (unused by reference)
    const float* bond  = (const float*)d_in[3];
    const float* projp = (const float*)d_in[4];
    const float* ssrc  = (const float*)d_in[5];
    const float* stgt  = (const float*)d_in[6];
    const float* skw   = (const float*)d_in[7];
    const float* cutp  = (const float*)d_in[8];  // value 0: any-dtype zero reads as 0.0f
    float* out = (float*)d_out;

    k0_weights<<<256, 256>>>(projp, skw);
    k1_gemm<<<dim3(128, 8), 256>>>(nodes);
    k2_scores<<<2048, 256>>>(ssrc, stgt);
    k3_mask<<<4096, 256>>>(degm, bond, cutp, out + (size_t)NN * 256);
    k5_colsum<<<128, 256>>>();

    const int smem4 = (8192 + 8704 + 128) * 4;   // 68096 bytes
    cudaFuncSetAttribute(k4_agg, cudaFuncAttributeMaxDynamicSharedMemorySize, smem4);
    k4_agg<<<dim3(128, 4), 256, smem4>>>(out);
}

// round 6
// speedup vs baseline: 2.1959x; 2.1959x over previous
#include <cuda_runtime.h>
#include <cstdint>

#define NN 4096
#define FIN 128
#define FO 64
#define HH 4
#define CC 512   // 256 proj cols (h*64+o) + 256 skip cols

// ---------------- scratch (static device globals; no allocation) ----------------
__device__ float  g_emask[(size_t)NN * NN];   // exp(mask), 64 MB
__device__ float  g_hidden[(size_t)NN * CC];  // [n][c]: c<256 proj, c>=256 skip (8 MB)
__device__ float  g_Wc[FIN * CC];             // combined weights [f][c]
__device__ float4 g_A[HH * NN];               // per (h,i): a, e^a, e^{0.2a}, -
__device__ float4 g_B[HH * NN];               // per (h,j): b, e^b, e^{0.2b}, invZ

// ---------------- helpers ----------------
__device__ __forceinline__ float maskf(float d, float b, float cut) {
    float wdm = d + b;
    return wdm > 0.f ? wdm : (b > cut ? (b + wdm) : -1e9f);
}
__device__ __forceinline__ float tf32f(float v) {
    uint32_t r;
    asm("cvt.rna.tf32.f32 %0, %1;" : "=r"(r) : "f"(v));
    return __uint_as_float(r);
}

// ---------------- K0: build combined weight matrix Wc[f][c] ----------------
__global__ void k0_weights(const float* __restrict__ projp, const float* __restrict__ skw) {
    int idx = blockIdx.x * 256 + threadIdx.x;   // 128*512 = 65536
    int f = idx >> 9, c = idx & 511;
    float v;
    if (c < 256) v = projp[(c >> 6) * (FIN * FO) + f * FO + (c & 63)];
    else         v = skw[(c - 256) * FIN + f];
    g_Wc[idx] = v;
}

// ---------------- K1: hidden = nodes[4096,128] @ Wc[128,512] ----------------
__global__ void __launch_bounds__(256) k1_gemm(const float* __restrict__ nodes) {
    __shared__ float sN[32 * 128];
    __shared__ float sW[128 * 64];
    const int t = threadIdx.x;
    const int i0 = blockIdx.x * 32;
    const int c0 = blockIdx.y * 64;
#pragma unroll
    for (int k = 0; k < 4; k++) {
        int q = t + k * 256;
        ((float4*)sN)[q] = ((const float4*)(nodes + (size_t)i0 * FIN))[q];
    }
#pragma unroll
    for (int k = 0; k < 8; k++) {
        int idx = t + k * 256;
        int f = idx >> 4, q = idx & 15;
        *(float4*)(sW + f * 64 + q * 4) = *(const float4*)(g_Wc + f * CC + c0 + q * 4);
    }
    __syncthreads();
    const int c = t & 63, rg = t >> 6;
    float acc[8] = {0.f,0.f,0.f,0.f,0.f,0.f,0.f,0.f};
#pragma unroll 4
    for (int f = 0; f < 128; f++) {
        float wv = sW[f * 64 + c];
#pragma unroll
        for (int r = 0; r < 8; r++)
            acc[r] += sN[(rg * 8 + r) * 128 + f] * wv;
    }
#pragma unroll
    for (int r = 0; r < 8; r++)
        g_hidden[(size_t)(i0 + rg * 8 + r) * CC + c0 + c] = acc[r];
}

// ---------------- K2: per-(h,n) scores a,b and their exponentials ----------------
__global__ void __launch_bounds__(256) k2_scores(const float* __restrict__ ssrc,
                                                 const float* __restrict__ stgt) {
    int w = blockIdx.x * 8 + (threadIdx.x >> 5);
    int lane = threadIdx.x & 31;
    int h = w >> 12, n = w & (NN - 1);
    const float* pr = g_hidden + (size_t)n * CC + h * FO;
    float p0 = pr[lane], p1 = pr[lane + 32];
    float sa = p0 * ssrc[h * FO + lane] + p1 * ssrc[h * FO + lane + 32];
    float sb = p0 * stgt[h * FO + lane] + p1 * stgt[h * FO + lane + 32];
#pragma unroll
    for (int o = 16; o > 0; o >>= 1) {
        sa += __shfl_xor_sync(0xffffffffu, sa, o);
        sb += __shfl_xor_sync(0xffffffffu, sb, o);
    }
    if (lane == 0) {
        g_A[h * NN + n] = make_float4(sa, __expf(sa), __expf(0.2f * sa), 0.f);
        g_B[h * NN + n] = make_float4(sb, __expf(sb), __expf(0.2f * sb), 0.f);
    }
}

// ---------------- K3: mask -> emask + LayerNorm(mask) in one row pass ----------------
__global__ void __launch_bounds__(256) k3_mask(const float* __restrict__ deg,
                                               const float* __restrict__ bond,
                                               const float* __restrict__ cutp,
                                               float* __restrict__ out_ln) {
    __shared__ float srow[NN];
    __shared__ float red1[256], red2[256];
    const int i = blockIdx.x;
    const int t = threadIdx.x;
    const float cut = cutp[0];
    const float4* d4 = (const float4*)(deg  + (size_t)i * NN);
    const float4* b4 = (const float4*)(bond + (size_t)i * NN);
    float4* e4 = (float4*)(g_emask + (size_t)i * NN);
    float s = 0.f, sq = 0.f;
#pragma unroll
    for (int k = 0; k < 4; k++) {
        int q = t + k * 256;
        float4 dv = d4[q], bv = b4[q];
        float4 mv;
        mv.x = maskf(dv.x, bv.x, cut);
        mv.y = maskf(dv.y, bv.y, cut);
        mv.z = maskf(dv.z, bv.z, cut);
        mv.w = maskf(dv.w, bv.w, cut);
        ((float4*)srow)[q] = mv;
        e4[q] = make_float4(__expf(mv.x), __expf(mv.y), __expf(mv.z), __expf(mv.w));
        s  += (mv.x + mv.y) + (mv.z + mv.w);
        sq += mv.x * mv.x + mv.y * mv.y + mv.z * mv.z + mv.w * mv.w;
    }
    red1[t] = s; red2[t] = sq;
    __syncthreads();
    for (int o = 128; o > 0; o >>= 1) {
        if (t < o) { red1[t] += red1[t + o]; red2[t] += red2[t + o]; }
        __syncthreads();
    }
    float mu  = red1[0] * (1.f / NN);
    float var = red2[0] * (1.f / NN) - mu * mu;
    float rs  = rsqrtf(var + 1e-5f);
    float4* o4 = (float4*)(out_ln + (size_t)i * NN);
#pragma unroll
    for (int k = 0; k < 4; k++) {
        int q = t + k * 256;
        float4 mv = ((float4*)srow)[q];
        o4[q] = make_float4((mv.x - mu) * rs, (mv.y - mu) * rs,
                            (mv.z - mu) * rs, (mv.w - mu) * rs);
    }
}

// ---------------- K5: column sums -> invZ[h][j] (no atomics) ----------------
__global__ void __launch_bounds__(256) k5_colsum() {
    __shared__ float4 sA[4 * 256];
    __shared__ float sS1[4 * 8 * 32];
    __shared__ float sS2[4 * 8 * 32];
    const int t = threadIdx.x;
    const int j0 = blockIdx.x * 32;
    const int col = t & 31, seg = t >> 5;
    const int j = j0 + col;
    float thr[4];
#pragma unroll
    for (int h = 0; h < 4; h++) thr[h] = -g_B[h * NN + j].x;
    float S1[4] = {0,0,0,0}, S2[4] = {0,0,0,0};
    for (int c0 = 0; c0 < NN; c0 += 256) {
        __syncthreads();
#pragma unroll
        for (int k = 0; k < 4; k++) {
            int idx = t + k * 256;
            sA[idx] = g_A[(idx >> 8) * NN + c0 + (idx & 255)];
        }
        __syncthreads();
        const float* emp = g_emask + (size_t)(c0 + seg * 32) * NN + j;
#pragma unroll 4
        for (int s = 0; s < 32; s++) {
            float em = emp[(size_t)s * NN];
#pragma unroll
            for (int h = 0; h < 4; h++) {
                float4 av = sA[h * 256 + seg * 32 + s];
                if (av.x > thr[h]) S1[h] += av.y * em; else S2[h] += av.z * em;
            }
        }
    }
#pragma unroll
    for (int h = 0; h < 4; h++) {
        sS1[(h * 8 + seg) * 32 + col] = S1[h];
        sS2[(h * 8 + seg) * 32 + col] = S2[h];
    }
    __syncthreads();
    if (t < 128) {
        int h = t >> 5, c = t & 31;
        float z1 = 0.f, z2 = 0.f;
#pragma unroll
        for (int s = 0; s < 8; s++) { z1 += sS1[(h * 8 + s) * 32 + c]; z2 += sS2[(h * 8 + s) * 32 + c]; }
        float4 Bv = g_B[h * NN + j0 + c];
        float Z = Bv.y * z1 + Bv.z * z2;
        ((float*)&g_B[h * NN + j0 + c])[3] = 1.0f / Z;
    }
}

// ---------------- K4: out = attn @ proj + skip, ELU via tf32 mma.sync ----------------
// Block = (64-row i-tile, head h), 256 threads (8 warps). Per 64-wide j-tile:
//   phase A: W[il][jl] = sel(a_i > -b_j)? eA*eB*invZ : eA2*eB2*invZ, * emask -> smem (tf32)
//            stage proj tile [64 j][64 f] -> smem (tf32)
//   phase B: warp w computes C[16x32] with m16n8k8 tf32 mma (A stride 68, B stride 72:
//            both fragment patterns are bank-conflict-free).
#define SWS 68
#define SPS 72
__global__ void __launch_bounds__(256) k4_mma(float* __restrict__ out) {
    __shared__ float sW[64 * SWS];
    __shared__ float sP[64 * SPS];
    __shared__ float4 sAr[64];
    const int t = threadIdx.x;
    const int i0 = blockIdx.x * 64;
    const int h  = blockIdx.y;
    const int lane = t & 31, w = t >> 5;
    const int g = lane >> 2, tg = lane & 3;
    const int mi = (w & 3) * 16, ni = (w >> 2) * 32;
    const int jl = t & 63, iseg = t >> 6;

    if (t < 64) sAr[t] = g_A[h * NN + i0 + t];
    float c0[4], c1[4], c2[4], c3[4];
#pragma unroll
    for (int n = 0; n < 4; n++) { c0[n] = 0.f; c1[n] = 0.f; c2[n] = 0.f; c3[n] = 0.f; }
    __syncthreads();

    for (int j0 = 0; j0 < NN; j0 += 64) {
        // ---- phase A: compute into registers (overlaps previous tile's mma) ----
        float4 Bv = g_B[h * NN + j0 + jl];
        const float thr = -Bv.x;
        const float e1 = Bv.y * Bv.w;   // e^b * invZ
        const float e2 = Bv.z * Bv.w;   // e^{0.2b} * invZ
        const float* emp = g_emask + (size_t)(i0 + iseg * 16) * NN + j0 + jl;
        float wv[16];
#pragma unroll
        for (int s = 0; s < 16; s++) {
            float em = emp[(size_t)s * NN];
            float4 av = sAr[iseg * 16 + s];
            wv[s] = ((av.x > thr) ? (av.y * e1) : (av.z * e2)) * em;
        }
        float4 pv[4];
#pragma unroll
        for (int k = 0; k < 4; k++) {
            int idx = t + k * 256;                // 1024 float4 = 64 rows x 16 q
            int jr = idx >> 4, q = idx & 15;
            pv[k] = *(const float4*)(g_hidden + (size_t)(j0 + jr) * CC + h * FO + q * 4);
        }
        __syncthreads();   // previous tile fully consumed
#pragma unroll
        for (int s = 0; s < 16; s++)
            sW[(iseg * 16 + s) * SWS + jl] = tf32f(wv[s]);
#pragma unroll
        for (int k = 0; k < 4; k++) {
            int idx = t + k * 256;
            int jr = idx >> 4, q = idx & 15;
            float4 tv = make_float4(tf32f(pv[k].x), tf32f(pv[k].y),
                                    tf32f(pv[k].z), tf32f(pv[k].w));
            *(float4*)(sP + jr * SPS + q * 4) = tv;
        }
        __syncthreads();   // tiles ready

        // ---- phase B: mma over K=64 (8 steps of k8) ----
#pragma unroll
        for (int kk = 0; kk < 8; kk++) {
            const float* aw = sW + mi * SWS + kk * 8;
            uint32_t a0 = __float_as_uint(aw[g * SWS + tg]);
            uint32_t a1 = __float_as_uint(aw[(g + 8) * SWS + tg]);
            uint32_t a2 = __float_as_uint(aw[g * SWS + tg + 4]);
            uint32_t a3 = __float_as_uint(aw[(g + 8) * SWS + tg + 4]);
            const float* bp = sP + (kk * 8) * SPS + ni;
#pragma unroll
            for (int nt = 0; nt < 4; nt++) {
                uint32_t b0 = __float_as_uint(bp[tg * SPS + nt * 8 + g]);
                uint32_t b1 = __float_as_uint(bp[(tg + 4) * SPS + nt * 8 + g]);
                asm volatile(
                    "mma.sync.aligned.m16n8k8.row.col.f32.tf32.tf32.f32 "
                    "{%0,%1,%2,%3}, {%4,%5,%6,%7}, {%8,%9}, {%0,%1,%2,%3};"
                    : "+f"(c0[nt]), "+f"(c1[nt]), "+f"(c2[nt]), "+f"(c3[nt])
                    : "r"(a0), "r"(a1), "r"(a2), "r"(a3), "r"(b0), "r"(b1));
            }
        }
    }

    // ---- epilogue: add skip, ELU, store ----
#pragma unroll
    for (int nt = 0; nt < 4; nt++) {
        int f = ni + nt * 8 + tg * 2;
        {
            int i = i0 + mi + g;
            const float2 sk = *(const float2*)(g_hidden + (size_t)i * CC + 256 + h * FO + f);
            float x0 = c0[nt] + sk.x, x1 = c1[nt] + sk.y;
            x0 = x0 > 0.f ? x0 : (__expf(x0) - 1.f);
            x1 = x1 > 0.f ? x1 : (__expf(x1) - 1.f);
            *(float2*)(out + (size_t)i * 256 + h * FO + f) = make_float2(x0, x1);
        }
        {
            int i = i0 + mi + g + 8;
            const float2 sk = *(const float2*)(g_hidden + (size_t)i * CC + 256 + h * FO + f);
            float x0 = c2[nt] + sk.x, x1 = c3[nt] + sk.y;
            x0 = x0 > 0.f ? x0 : (__expf(x0) - 1.f);
            x1 = x1 > 0.f ? x1 : (__expf(x1) - 1.f);
            *(float2*)(out + (size_t)i * 256 + h * FO + f) = make_float2(x0, x1);
        }
    }
}

// ---------------- launcher ----------------
extern "C" void kernel_launch(void* const* d_in, const int* in_sizes, int n_in,
                              void* d_out, int out_size) {
    const float* nodes = (const float*)d_in[0];
    const float* degm  = (const float*)d_in[1];
    // d_in[2] = edges_features_distance (unused by reference)
    const float* bond  = (const float*)d_in[3];
    const float* projp = (const float*)d_in[4];
    const float* ssrc  = (const float*)d_in[5];
    const float* stgt  = (const float*)d_in[6];
    const float* skw   = (const float*)d_in[7];
    const float* cutp  = (const float*)d_in[8];
    float* out = (float*)d_out;

    k0_weights<<<256, 256>>>(projp, skw);
    k1_gemm<<<dim3(128, 8), 256>>>(nodes);
    k2_scores<<<2048, 256>>>(ssrc, stgt);
    k3_mask<<<4096, 256>>>(degm, bond, cutp, out + (size_t)NN * 256);
    k5_colsum<<<128, 256>>>();
    k4_mma<<<dim3(64, 4), 256>>>(out);
}

// round 7
// speedup vs baseline: 2.9017x; 1.3214x over previous
#include <cuda_runtime.h>
#include <cuda_bf16.h>
#include <cstdint>

#define NN 4096
#define FIN 128
#define FO 64
#define HH 4
#define CC 512   // 256 proj cols (h*64+o) + 256 skip cols

// ---------------- scratch (static device globals; no allocation) ----------------
__device__ uint32_t g_em[(size_t)NN * NN / 2];     // exp(mask) bf16 pairs (32 MB)
__device__ float    g_hidden[(size_t)NN * CC];     // [n][c]: c<256 proj, c>=256 skip (8 MB)
__device__ float    g_Wc[FIN * CC];                // combined weights [f][c]
__device__ float4   g_A[HH * NN];                  // per (h,i): a, e^a, e^{0.2a}, -
__device__ float4   g_B[HH * NN];                  // per (h,j): b, e^b, e^{0.2b}, invZ
__device__ uint32_t g_projT[(size_t)256 * (NN/2)]; // projT bf16: row c=h*64+f, cols j (2 MB)
__device__ float    g_part[(size_t)8 * NN * 256];  // per-j-chunk partial outputs (32 MB)

// ---------------- helpers ----------------
__device__ __forceinline__ float maskf(float d, float b, float cut) {
    float wdm = d + b;
    return wdm > 0.f ? wdm : (b > cut ? (b + wdm) : -1e9f);
}
__device__ __forceinline__ uint32_t packbf2(float lo, float hi) {
    __nv_bfloat162 p = __floats2bfloat162_rn(lo, hi);
    return *(uint32_t*)&p;
}

// ---------------- K0: build combined weight matrix Wc[f][c] ----------------
__global__ void k0_weights(const float* __restrict__ projp, const float* __restrict__ skw) {
    int idx = blockIdx.x * 256 + threadIdx.x;   // 128*512 = 65536
    int f = idx >> 9, c = idx & 511;
    float v;
    if (c < 256) v = projp[(c >> 6) * (FIN * FO) + f * FO + (c & 63)];
    else         v = skw[(c - 256) * FIN + f];
    g_Wc[idx] = v;
}

// ---------------- K1: hidden = nodes[4096,128] @ Wc[128,512] ----------------
__global__ void __launch_bounds__(256) k1_gemm(const float* __restrict__ nodes) {
    __shared__ float sN[32 * 128];
    __shared__ float sW[128 * 64];
    const int t = threadIdx.x;
    const int i0 = blockIdx.x * 32;
    const int c0 = blockIdx.y * 64;
#pragma unroll
    for (int k = 0; k < 4; k++) {
        int q = t + k * 256;
        ((float4*)sN)[q] = ((const float4*)(nodes + (size_t)i0 * FIN))[q];
    }
#pragma unroll
    for (int k = 0; k < 8; k++) {
        int idx = t + k * 256;
        int f = idx >> 4, q = idx & 15;
        *(float4*)(sW + f * 64 + q * 4) = *(const float4*)(g_Wc + f * CC + c0 + q * 4);
    }
    __syncthreads();
    const int c = t & 63, rg = t >> 6;
    float acc[8] = {0.f,0.f,0.f,0.f,0.f,0.f,0.f,0.f};
#pragma unroll 4
    for (int f = 0; f < 128; f++) {
        float wv = sW[f * 64 + c];
#pragma unroll
        for (int r = 0; r < 8; r++)
            acc[r] += sN[(rg * 8 + r) * 128 + f] * wv;
    }
#pragma unroll
    for (int r = 0; r < 8; r++)
        g_hidden[(size_t)(i0 + rg * 8 + r) * CC + c0 + c] = acc[r];
}

// ---------------- K1b: transpose proj -> g_projT bf16 [c][j] ----------------
__global__ void __launch_bounds__(256) k1b_transpose() {
    __shared__ float sT[64 * 65];
    const int t = threadIdx.x;
    const int j0 = blockIdx.x * 64;
    const int c0 = blockIdx.y * 64;
#pragma unroll
    for (int k = 0; k < 4; k++) {
        int idx = t + k * 256;
        int jr = idx >> 4, q = idx & 15;
        float4 v = *(const float4*)(g_hidden + (size_t)(j0 + jr) * CC + c0 + q * 4);
        sT[(q * 4 + 0) * 65 + jr] = v.x;
        sT[(q * 4 + 1) * 65 + jr] = v.y;
        sT[(q * 4 + 2) * 65 + jr] = v.z;
        sT[(q * 4 + 3) * 65 + jr] = v.w;
    }
    __syncthreads();
#pragma unroll
    for (int k = 0; k < 8; k++) {
        int idx = t + k * 256;
        int cr = idx >> 5, p = idx & 31;
        g_projT[(size_t)(c0 + cr) * (NN/2) + (j0 >> 1) + p] =
            packbf2(sT[cr * 65 + 2 * p], sT[cr * 65 + 2 * p + 1]);
    }
}

// ---------------- K2: per-(h,n) scores a,b and their exponentials ----------------
__global__ void __launch_bounds__(256) k2_scores(const float* __restrict__ ssrc,
                                                 const float* __restrict__ stgt) {
    int w = blockIdx.x * 8 + (threadIdx.x >> 5);
    int lane = threadIdx.x & 31;
    int h = w >> 12, n = w & (NN - 1);
    const float* pr = g_hidden + (size_t)n * CC + h * FO;
    float p0 = pr[lane], p1 = pr[lane + 32];
    float sa = p0 * ssrc[h * FO + lane] + p1 * ssrc[h * FO + lane + 32];
    float sb = p0 * stgt[h * FO + lane] + p1 * stgt[h * FO + lane + 32];
#pragma unroll
    for (int o = 16; o > 0; o >>= 1) {
        sa += __shfl_xor_sync(0xffffffffu, sa, o);
        sb += __shfl_xor_sync(0xffffffffu, sb, o);
    }
    if (lane == 0) {
        g_A[h * NN + n] = make_float4(sa, __expf(sa), __expf(0.2f * sa), 0.f);
        g_B[h * NN + n] = make_float4(sb, __expf(sb), __expf(0.2f * sb), 0.f);
    }
}

// ---------------- K3: mask -> emask(bf16) + LayerNorm(mask) in one row pass ----------------
__global__ void __launch_bounds__(256) k3_mask(const float* __restrict__ deg,
                                               const float* __restrict__ bond,
                                               const float* __restrict__ cutp,
                                               float* __restrict__ out_ln) {
    __shared__ float srow[NN];
    __shared__ float red1[256], red2[256];
    const int i = blockIdx.x;
    const int t = threadIdx.x;
    const float cut = cutp[0];
    const float4* d4 = (const float4*)(deg  + (size_t)i * NN);
    const float4* b4 = (const float4*)(bond + (size_t)i * NN);
    uint2* e2 = (uint2*)(g_em + (size_t)i * (NN/2));
    float s = 0.f, sq = 0.f;
#pragma unroll
    for (int k = 0; k < 4; k++) {
        int q = t + k * 256;
        float4 dv = d4[q], bv = b4[q];
        float4 mv;
        mv.x = maskf(dv.x, bv.x, cut);
        mv.y = maskf(dv.y, bv.y, cut);
        mv.z = maskf(dv.z, bv.z, cut);
        mv.w = maskf(dv.w, bv.w, cut);
        ((float4*)srow)[q] = mv;
        uint2 ev;
        ev.x = packbf2(__expf(mv.x), __expf(mv.y));
        ev.y = packbf2(__expf(mv.z), __expf(mv.w));
        e2[q] = ev;
        s  += (mv.x + mv.y) + (mv.z + mv.w);
        sq += mv.x * mv.x + mv.y * mv.y + mv.z * mv.z + mv.w * mv.w;
    }
    red1[t] = s; red2[t] = sq;
    __syncthreads();
    for (int o = 128; o > 0; o >>= 1) {
        if (t < o) { red1[t] += red1[t + o]; red2[t] += red2[t + o]; }
        __syncthreads();
    }
    float mu  = red1[0] * (1.f / NN);
    float var = red2[0] * (1.f / NN) - mu * mu;
    float rs  = rsqrtf(var + 1e-5f);
    float4* o4 = (float4*)(out_ln + (size_t)i * NN);
#pragma unroll
    for (int k = 0; k < 4; k++) {
        int q = t + k * 256;
        float4 mv = ((float4*)srow)[q];
        o4[q] = make_float4((mv.x - mu) * rs, (mv.y - mu) * rs,
                            (mv.z - mu) * rs, (mv.w - mu) * rs);
    }
}

// ---------------- K5: column sums over i -> invZ[h][j] ----------------
__global__ void __launch_bounds__(256) k5_colsum() {
    __shared__ float4 sA[4 * 256];
    __shared__ float sS1[4 * 8 * 32];
    __shared__ float sS2[4 * 8 * 32];
    const int t = threadIdx.x;
    const int j0 = blockIdx.x * 32;
    const int col = t & 31, seg = t >> 5;
    const int j = j0 + col;
    const __nv_bfloat16* emb = (const __nv_bfloat16*)g_em;
    float thr[4];
#pragma unroll
    for (int h = 0; h < 4; h++) thr[h] = -g_B[h * NN + j].x;
    float S1[4] = {0,0,0,0}, S2[4] = {0,0,0,0};
    for (int c0 = 0; c0 < NN; c0 += 256) {
        __syncthreads();
#pragma unroll
        for (int k = 0; k < 4; k++) {
            int idx = t + k * 256;
            sA[idx] = g_A[(idx >> 8) * NN + c0 + (idx & 255)];
        }
        __syncthreads();
        const __nv_bfloat16* emp = emb + (size_t)(c0 + seg * 32) * NN + j;
#pragma unroll 4
        for (int s = 0; s < 32; s++) {
            float em = __bfloat162float(emp[(size_t)s * NN]);
#pragma unroll
            for (int h = 0; h < 4; h++) {
                float4 av = sA[h * 256 + seg * 32 + s];
                if (av.x > thr[h]) S1[h] += av.y * em; else S2[h] += av.z * em;
            }
        }
    }
#pragma unroll
    for (int h = 0; h < 4; h++) {
        sS1[(h * 8 + seg) * 32 + col] = S1[h];
        sS2[(h * 8 + seg) * 32 + col] = S2[h];
    }
    __syncthreads();
    if (t < 128) {
        int h = t >> 5, c = t & 31;
        float z1 = 0.f, z2 = 0.f;
#pragma unroll
        for (int s = 0; s < 8; s++) { z1 += sS1[(h * 8 + s) * 32 + c]; z2 += sS2[(h * 8 + s) * 32 + c]; }
        float4 Bv = g_B[h * NN + j0 + c];
        float Z = Bv.y * z1 + Bv.z * z2;
        ((float*)&g_B[h * NN + j0 + c])[3] = 1.0f / Z;
    }
}

// ---------------- K4: attn @ proj for ALL 4 heads via bf16 m16n8k16 mma ----------------
// Grid (64 i-tiles, 8 j-chunks of 512). Per 64-j tile: em tile loaded ONCE, W_h built
// for 4 heads in smem (bf16), projT tiles copied bf16; 8 warps each own C=16x32 per head.
// Partials to g_part[jc]; k6 reduces.
#define SU 36   // u32 stride of bf16 tiles (72 bf16): conflict-free (4g+tg) bank pattern
__global__ void __launch_bounds__(256) k4_mma() {
    extern __shared__ uint32_t smem[];
    uint32_t* sW  = smem;                        // [4][64*SU]
    uint32_t* sPT = smem + 4 * 64 * SU;          // [4][64*SU]
    float4*   sAr = (float4*)(smem + 8 * 64 * SU); // [4][64]
    const int t = threadIdx.x;
    const int i0 = blockIdx.x * 64;
    const int jc = blockIdx.y;
    const int lane = t & 31, w = t >> 5;
    const int g = lane >> 2, tg = lane & 3;
    const int mi = (w & 3) * 16, ni = (w >> 2) * 32;
    const int p = lane;      // j-pair 0..31
    const int iseg = w;      // warp -> rows iseg*8..+8

    sAr[t] = g_A[(t >> 6) * NN + i0 + (t & 63)];
    float acc[4][4][4];
#pragma unroll
    for (int h = 0; h < 4; h++)
#pragma unroll
        for (int n = 0; n < 4; n++)
#pragma unroll
            for (int r = 0; r < 4; r++) acc[h][n][r] = 0.f;
    __syncthreads();

    for (int jt = 0; jt < 8; jt++) {
        const int j0 = jc * 512 + jt * 64;
        // ---- register loads (overlap with prev tile's mma via other CTAs/warps) ----
        uint32_t emv[8];
        const uint32_t* emrow = g_em + (size_t)(i0 + iseg * 8) * (NN/2) + (j0 >> 1) + p;
#pragma unroll
        for (int s = 0; s < 8; s++) emv[s] = emrow[(size_t)s * (NN/2)];
        float4 BL[4], BH[4];
#pragma unroll
        for (int h = 0; h < 4; h++) {
            BL[h] = g_B[h * NN + j0 + 2 * p];
            BH[h] = g_B[h * NN + j0 + 2 * p + 1];
        }
        uint4 pv[8];
        {
            const uint4* src = (const uint4*)g_projT;   // [256][512] uint4
#pragma unroll
            for (int k = 0; k < 8; k++) {
                int idx = t + k * 256;
                int r = idx >> 3, q = idx & 7;
                pv[k] = src[(size_t)r * 512 + (j0 >> 3) + q];
            }
        }
        __syncthreads();   // previous tile fully consumed
        // ---- stage projT ----
#pragma unroll
        for (int k = 0; k < 8; k++) {
            int idx = t + k * 256;
            int r = idx >> 3, q = idx & 7;
            *(uint4*)(sPT + (size_t)(r >> 6) * (64 * SU) + (r & 63) * SU + q * 4) = pv[k];
        }
        // ---- compute & stage W for 4 heads ----
#pragma unroll
        for (int h = 0; h < 4; h++) {
            const float thrL = -BL[h].x, e1L = BL[h].y * BL[h].w, e2L = BL[h].z * BL[h].w;
            const float thrH = -BH[h].x, e1H = BH[h].y * BH[h].w, e2H = BH[h].z * BH[h].w;
#pragma unroll
            for (int s = 0; s < 8; s++) {
                float4 av = sAr[h * 64 + iseg * 8 + s];
                __nv_bfloat162 eb = *(__nv_bfloat162*)&emv[s];
                float wlo = ((av.x > thrL) ? av.y * e1L : av.z * e2L) * __low2float(eb);
                float whi = ((av.x > thrH) ? av.y * e1H : av.z * e2H) * __high2float(eb);
                sW[h * (64 * SU) + (iseg * 8 + s) * SU + p] = packbf2(wlo, whi);
            }
        }
        __syncthreads();   // tiles ready
        // ---- mma: 4 heads x (K=64 -> 4 k16 steps) x 4 n-tiles ----
#pragma unroll
        for (int h = 0; h < 4; h++) {
            const uint32_t* Wb = sW + h * (64 * SU);
            const uint32_t* Pb = sPT + h * (64 * SU);
#pragma unroll
            for (int kk = 0; kk < 4; kk++) {
                uint32_t a0 = Wb[(mi + g) * SU + kk * 8 + tg];
                uint32_t a1 = Wb[(mi + g + 8) * SU + kk * 8 + tg];
                uint32_t a2 = Wb[(mi + g) * SU + kk * 8 + tg + 4];
                uint32_t a3 = Wb[(mi + g + 8) * SU + kk * 8 + tg + 4];
#pragma unroll
                for (int nt = 0; nt < 4; nt++) {
                    uint32_t b0 = Pb[(ni + nt * 8 + g) * SU + kk * 8 + tg];
                    uint32_t b1 = Pb[(ni + nt * 8 + g) * SU + kk * 8 + tg + 4];
                    asm volatile(
                        "mma.sync.aligned.m16n8k16.row.col.f32.bf16.bf16.f32 "
                        "{%0,%1,%2,%3}, {%4,%5,%6,%7}, {%8,%9}, {%0,%1,%2,%3};"
                        : "+f"(acc[h][nt][0]), "+f"(acc[h][nt][1]),
                          "+f"(acc[h][nt][2]), "+f"(acc[h][nt][3])
                        : "r"(a0), "r"(a1), "r"(a2), "r"(a3), "r"(b0), "r"(b1));
                }
            }
        }
    }
    // ---- store partials ----
    float* pb = g_part + (size_t)jc * NN * 256;
#pragma unroll
    for (int h = 0; h < 4; h++)
#pragma unroll
        for (int nt = 0; nt < 4; nt++) {
            int col = h * 64 + ni + nt * 8 + 2 * tg;
            *(float2*)(pb + (size_t)(i0 + mi + g) * 256 + col) =
                make_float2(acc[h][nt][0], acc[h][nt][1]);
            *(float2*)(pb + (size_t)(i0 + mi + g + 8) * 256 + col) =
                make_float2(acc[h][nt][2], acc[h][nt][3]);
        }
}

// ---------------- K6: reduce partials + skip + ELU ----------------
__global__ void __launch_bounds__(256) k6_epilogue(float* __restrict__ out) {
    int gid = blockIdx.x * 256 + threadIdx.x;    // 262144 float4
    float4 s = make_float4(0.f, 0.f, 0.f, 0.f);
#pragma unroll
    for (int jc = 0; jc < 8; jc++) {
        float4 v = ((const float4*)(g_part + ((size_t)jc << 20)))[gid];
        s.x += v.x; s.y += v.y; s.z += v.z; s.w += v.w;
    }
    int i = gid >> 6, c = (gid & 63) * 4;
    float4 sk = *(const float4*)(g_hidden + (size_t)i * CC + 256 + c);
    float x0 = s.x + sk.x, x1 = s.y + sk.y, x2 = s.z + sk.z, x3 = s.w + sk.w;
    x0 = x0 > 0.f ? x0 : (__expf(x0) - 1.f);
    x1 = x1 > 0.f ? x1 : (__expf(x1) - 1.f);
    x2 = x2 > 0.f ? x2 : (__expf(x2) - 1.f);
    x3 = x3 > 0.f ? x3 : (__expf(x3) - 1.f);
    ((float4*)out)[gid] = make_float4(x0, x1, x2, x3);
}

// ---------------- launcher ----------------
extern "C" void kernel_launch(void* const* d_in, const int* in_sizes, int n_in,
                              void* d_out, int out_size) {
    const float* nodes = (const float*)d_in[0];
    const float* degm  = (const float*)d_in[1];
    // d_in[2] = edges_features_distance (unused by reference)
    const float* bond  = (const float*)d_in[3];
    const float* projp = (const float*)d_in[4];
    const float* ssrc  = (const float*)d_in[5];
    const float* stgt  = (const float*)d_in[6];
    const float* skw   = (const float*)d_in[7];
    const float* cutp  = (const float*)d_in[8];
    float* out = (float*)d_out;

    k0_weights<<<256, 256>>>(projp, skw);
    k1_gemm<<<dim3(128, 8), 256>>>(nodes);
    k1b_transpose<<<dim3(64, 4), 256>>>();
    k2_scores<<<2048, 256>>>(ssrc, stgt);
    k3_mask<<<4096, 256>>>(degm, bond, cutp, out + (size_t)NN * 256);
    k5_colsum<<<128, 256>>>();

    const int smem4 = (8 * 64 * SU) * 4 + 4 * 64 * 16;   // 77824 bytes
    cudaFuncSetAttribute(k4_mma, cudaFuncAttributeMaxDynamicSharedMemorySize, smem4);
    k4_mma<<<dim3(64, 8), 256, smem4>>>();
    k6_epilogue<<<1024, 256>>>(out);
}

// round 9
// speedup vs baseline: 3.2404x; 1.1167x over previous
#include <cuda_runtime.h>
#include <cuda_bf16.h>
#include <cstdint>

#define NN 4096
#define FIN 128
#define FO 64
#define HH 4
#define CC 512   // 256 proj cols (h*64+o) + 256 skip cols

// ---------------- scratch (static device globals; no allocation) ----------------
__device__ uint32_t g_em[(size_t)NN * NN / 2];     // exp(mask) bf16 pairs (32 MB)
__device__ float    g_hidden[(size_t)NN * CC];     // [n][c]: c<256 proj, c>=256 skip (8 MB)
__device__ float    g_Wc[FIN * CC];                // combined weights [f][c]
__device__ float4   g_A[HH * NN];                  // per (h,i): a, e^a, e^{0.2a}, -
__device__ float4   g_B[HH * NN];                  // per (h,j): b, e^b, e^{0.2b}, invZ
__device__ uint32_t g_projT[(size_t)256 * (NN/2)]; // projT bf16: row c=h*64+f, cols j (2 MB)
__device__ uint2    g_Bp[HH * NN];                 // packed bf16 (thr,e1),(e2,0) per (h,j)
__device__ float    g_part[(size_t)8 * NN * 256];  // per-j-chunk partial outputs (32 MB)

// ---------------- helpers ----------------
__device__ __forceinline__ float maskf(float d, float b, float cut) {
    float wdm = d + b;
    return wdm > 0.f ? wdm : (b > cut ? (b + wdm) : -1e9f);
}
__device__ __forceinline__ uint32_t packbf2(float lo, float hi) {
    __nv_bfloat162 p = __floats2bfloat162_rn(lo, hi);
    return *(uint32_t*)&p;
}
__device__ __forceinline__ uint32_t smem_u32(const void* p) {
    uint32_t a;
    asm("{ .reg .u64 t; cvta.to.shared.u64 t, %1; cvt.u32.u64 %0, t; }" : "=r"(a) : "l"(p));
    return a;
}
__device__ __forceinline__ void ldsm4(uint32_t& r0, uint32_t& r1, uint32_t& r2, uint32_t& r3,
                                      uint32_t addr) {
    asm volatile("ldmatrix.sync.aligned.m8n8.x4.shared.b16 {%0,%1,%2,%3}, [%4];"
                 : "=r"(r0), "=r"(r1), "=r"(r2), "=r"(r3) : "r"(addr));
}

// ---------------- K0: build combined weight matrix Wc[f][c] ----------------
__global__ void k0_weights(const float* __restrict__ projp, const float* __restrict__ skw) {
    int idx = blockIdx.x * 256 + threadIdx.x;
    int f = idx >> 9, c = idx & 511;
    float v;
    if (c < 256) v = projp[(c >> 6) * (FIN * FO) + f * FO + (c & 63)];
    else         v = skw[(c - 256) * FIN + f];
    g_Wc[idx] = v;
}

// ---------------- K1: hidden = nodes[4096,128] @ Wc[128,512] ----------------
__global__ void __launch_bounds__(256) k1_gemm(const float* __restrict__ nodes) {
    __shared__ float sN[32 * 128];
    __shared__ float sW[128 * 64];
    const int t = threadIdx.x;
    const int i0 = blockIdx.x * 32;
    const int c0 = blockIdx.y * 64;
#pragma unroll
    for (int k = 0; k < 4; k++) {
        int q = t + k * 256;
        ((float4*)sN)[q] = ((const float4*)(nodes + (size_t)i0 * FIN))[q];
    }
#pragma unroll
    for (int k = 0; k < 8; k++) {
        int idx = t + k * 256;
        int f = idx >> 4, q = idx & 15;
        *(float4*)(sW + f * 64 + q * 4) = *(const float4*)(g_Wc + f * CC + c0 + q * 4);
    }
    __syncthreads();
    const int c = t & 63, rg = t >> 6;
    float acc[8] = {0.f,0.f,0.f,0.f,0.f,0.f,0.f,0.f};
#pragma unroll 4
    for (int f = 0; f < 128; f++) {
        float wv = sW[f * 64 + c];
#pragma unroll
        for (int r = 0; r < 8; r++)
            acc[r] += sN[(rg * 8 + r) * 128 + f] * wv;
    }
#pragma unroll
    for (int r = 0; r < 8; r++)
        g_hidden[(size_t)(i0 + rg * 8 + r) * CC + c0 + c] = acc[r];
}

// ---------------- K1b: transpose proj -> g_projT bf16 [c][j] ----------------
__global__ void __launch_bounds__(256) k1b_transpose() {
    __shared__ float sT[64 * 65];
    const int t = threadIdx.x;
    const int j0 = blockIdx.x * 64;
    const int c0 = blockIdx.y * 64;
#pragma unroll
    for (int k = 0; k < 4; k++) {
        int idx = t + k * 256;
        int jr = idx >> 4, q = idx & 15;
        float4 v = *(const float4*)(g_hidden + (size_t)(j0 + jr) * CC + c0 + q * 4);
        sT[(q * 4 + 0) * 65 + jr] = v.x;
        sT[(q * 4 + 1) * 65 + jr] = v.y;
        sT[(q * 4 + 2) * 65 + jr] = v.z;
        sT[(q * 4 + 3) * 65 + jr] = v.w;
    }
    __syncthreads();
#pragma unroll
    for (int k = 0; k < 8; k++) {
        int idx = t + k * 256;
        int cr = idx >> 5, p = idx & 31;
        g_projT[(size_t)(c0 + cr) * (NN/2) + (j0 >> 1) + p] =
            packbf2(sT[cr * 65 + 2 * p], sT[cr * 65 + 2 * p + 1]);
    }
}

// ---------------- K1d: pack softmax B-params to bf16 ----------------
__global__ void k1d_bp() {
    int idx = blockIdx.x * 256 + threadIdx.x;   // 16384
    float4 Bv = g_B[idx];
    g_Bp[idx] = make_uint2(packbf2(-Bv.x, Bv.y * Bv.w), packbf2(Bv.z * Bv.w, 0.f));
}

// ---------------- K2: per-(h,n) scores a,b and their exponentials ----------------
__global__ void __launch_bounds__(256) k2_scores(const float* __restrict__ ssrc,
                                                 const float* __restrict__ stgt) {
    int w = blockIdx.x * 8 + (threadIdx.x >> 5);
    int lane = threadIdx.x & 31;
    int h = w >> 12, n = w & (NN - 1);
    const float* pr = g_hidden + (size_t)n * CC + h * FO;
    float p0 = pr[lane], p1 = pr[lane + 32];
    float sa = p0 * ssrc[h * FO + lane] + p1 * ssrc[h * FO + lane + 32];
    float sb = p0 * stgt[h * FO + lane] + p1 * stgt[h * FO + lane + 32];
#pragma unroll
    for (int o = 16; o > 0; o >>= 1) {
        sa += __shfl_xor_sync(0xffffffffu, sa, o);
        sb += __shfl_xor_sync(0xffffffffu, sb, o);
    }
    if (lane == 0) {
        g_A[h * NN + n] = make_float4(sa, __expf(sa), __expf(0.2f * sa), 0.f);
        g_B[h * NN + n] = make_float4(sb, __expf(sb), __expf(0.2f * sb), 0.f);
    }
}

// ---------------- K3: mask -> emask(bf16) + LayerNorm(mask) ----------------
__global__ void __launch_bounds__(256) k3_mask(const float* __restrict__ deg,
                                               const float* __restrict__ bond,
                                               const float* __restrict__ cutp,
                                               float* __restrict__ out_ln) {
    __shared__ float srow[NN];
    __shared__ float red1[256], red2[256];
    const int i = blockIdx.x;
    const int t = threadIdx.x;
    const float cut = cutp[0];
    const float4* d4 = (const float4*)(deg  + (size_t)i * NN);
    const float4* b4 = (const float4*)(bond + (size_t)i * NN);
    uint2* e2 = (uint2*)(g_em + (size_t)i * (NN/2));
    float s = 0.f, sq = 0.f;
#pragma unroll
    for (int k = 0; k < 4; k++) {
        int q = t + k * 256;
        float4 dv = d4[q], bv = b4[q];
        float4 mv;
        mv.x = maskf(dv.x, bv.x, cut);
        mv.y = maskf(dv.y, bv.y, cut);
        mv.z = maskf(dv.z, bv.z, cut);
        mv.w = maskf(dv.w, bv.w, cut);
        ((float4*)srow)[q] = mv;
        uint2 ev;
        ev.x = packbf2(__expf(mv.x), __expf(mv.y));
        ev.y = packbf2(__expf(mv.z), __expf(mv.w));
        e2[q] = ev;
        s  += (mv.x + mv.y) + (mv.z + mv.w);
        sq += mv.x * mv.x + mv.y * mv.y + mv.z * mv.z + mv.w * mv.w;
    }
    red1[t] = s; red2[t] = sq;
    __syncthreads();
    for (int o = 128; o > 0; o >>= 1) {
        if (t < o) { red1[t] += red1[t + o]; red2[t] += red2[t + o]; }
        __syncthreads();
    }
    float mu  = red1[0] * (1.f / NN);
    float var = red2[0] * (1.f / NN) - mu * mu;
    float rs  = rsqrtf(var + 1e-5f);
    float4* o4 = (float4*)(out_ln + (size_t)i * NN);
#pragma unroll
    for (int k = 0; k < 4; k++) {
        int q = t + k * 256;
        float4 mv = ((float4*)srow)[q];
        o4[q] = make_float4((mv.x - mu) * rs, (mv.y - mu) * rs,
                            (mv.z - mu) * rs, (mv.w - mu) * rs);
    }
}

// ---------------- K5: column sums over i -> invZ[h][j] ----------------
__global__ void __launch_bounds__(256) k5_colsum() {
    __shared__ float4 sA[4 * 256];
    __shared__ float sS1[4 * 8 * 32];
    __shared__ float sS2[4 * 8 * 32];
    const int t = threadIdx.x;
    const int j0 = blockIdx.x * 32;
    const int col = t & 31, seg = t >> 5;
    const int j = j0 + col;
    const __nv_bfloat16* emb = (const __nv_bfloat16*)g_em;
    float thr[4];
#pragma unroll
    for (int h = 0; h < 4; h++) thr[h] = -g_B[h * NN + j].x;
    float S1[4] = {0,0,0,0}, S2[4] = {0,0,0,0};
    for (int c0 = 0; c0 < NN; c0 += 256) {
        __syncthreads();
#pragma unroll
        for (int k = 0; k < 4; k++) {
            int idx = t + k * 256;
            sA[idx] = g_A[(idx >> 8) * NN + c0 + (idx & 255)];
        }
        __syncthreads();
        const __nv_bfloat16* emp = emb + (size_t)(c0 + seg * 32) * NN + j;
#pragma unroll 4
        for (int s = 0; s < 32; s++) {
            float em = __bfloat162float(emp[(size_t)s * NN]);
#pragma unroll
            for (int h = 0; h < 4; h++) {
                float4 av = sA[h * 256 + seg * 32 + s];
                if (av.x > thr[h]) S1[h] += av.y * em; else S2[h] += av.z * em;
            }
        }
    }
#pragma unroll
    for (int h = 0; h < 4; h++) {
        sS1[(h * 8 + seg) * 32 + col] = S1[h];
        sS2[(h * 8 + seg) * 32 + col] = S2[h];
    }
    __syncthreads();
    if (t < 128) {
        int h = t >> 5, c = t & 31;
        float z1 = 0.f, z2 = 0.f;
#pragma unroll
        for (int s = 0; s < 8; s++) { z1 += sS1[(h * 8 + s) * 32 + c]; z2 += sS2[(h * 8 + s) * 32 + c]; }
        float4 Bv = g_B[h * NN + j0 + c];
        float Z = Bv.y * z1 + Bv.z * z2;
        ((float*)&g_B[h * NN + j0 + c])[3] = 1.0f / Z;
    }
}

// ---------------- K4: attn @ proj (4 heads) via bf16 m16n8k16 + ldmatrix ----------------
// Grid (64 i-tiles of 64, 8 j-chunks of 512), 256 threads. smem layout (bytes):
//   sW  [4][64 rows][36 u32]  @ 0       (attention weights, bf16, stride 144B)
//   sPT [256 rows c][36 u32]  @ 36864   (projT tile, bf16, rows c = h*64+f)
//   sBp [4][512] uint2        @ 73728   (bf16 thr,e1,e2 per (h,j) of this chunk)
//   sAr [4][64] float4        @ 90112   (a, e^a, e^{0.2a} per (h,i))
#define SW_OFF  0
#define SPT_OFF 36864
#define SBP_OFF 73728
#define SAR_OFF 90112
#define SM4_TOT 94208
__global__ void __launch_bounds__(256) k4_mma() {
    extern __shared__ char smem[];
    const uint32_t smb = smem_u32(smem);
    uint32_t* sW  = (uint32_t*)(smem + SW_OFF);
    uint2*    sBp = (uint2*)(smem + SBP_OFF);
    float4*   sAr = (float4*)(smem + SAR_OFF);
    const int t = threadIdx.x;
    const int i0 = blockIdx.x * 64;
    const int jc = blockIdx.y;
    const int lane = t & 31, w = t >> 5;
    const int g = lane >> 2, tg = lane & 3;
    const int mi = (w & 3) * 16, ni = (w >> 2) * 32;
    const int p = lane;     // j-pair 0..31 (w-gen)
    const int iseg = w;     // warp -> rows iseg*8..+8 (w-gen)

    // ---- prologue: stage sAr, sBp ----
    sAr[t] = g_A[(t >> 6) * NN + i0 + (t & 63)];
#pragma unroll
    for (int k = 0; k < 8; k++) {
        int idx = t + k * 256;
        sBp[idx] = g_Bp[(idx >> 9) * NN + jc * 512 + (idx & 511)];
    }
    float acc[4][4][4];
#pragma unroll
    for (int h = 0; h < 4; h++)
#pragma unroll
        for (int n = 0; n < 4; n++)
#pragma unroll
            for (int r = 0; r < 4; r++) acc[h][n][r] = 0.f;

    // ldmatrix lane address offsets (bytes)
    const uint32_t aA  = smb + SW_OFF + (mi + (lane & 15)) * 144 + (lane >> 4) * 16;
    const uint32_t aB  = smb + SPT_OFF +
                         (ni + ((lane >> 4) & 1) * 8 + (lane & 7)) * 144 +
                         ((lane >> 3) & 1) * 16;
    const uint32_t* emrow = g_em + (size_t)(i0 + iseg * 8) * (NN/2) + jc * 256 + p;

    // prefetch em for tile 0
    uint32_t emv[8];
#pragma unroll
    for (int s = 0; s < 8; s++) emv[s] = emrow[(size_t)s * (NN/2)];
    __syncthreads();

    for (int jt = 0; jt < 8; jt++) {
        // ---- stage projT tile (L2-hot) + compute w -> sW ----
        // (previous tile's mma finished at the barrier ending last iteration)
#pragma unroll
        for (int k = 0; k < 8; k++) {
            int idx = t + k * 256;
            int r = idx >> 3, q = idx & 7;
            uint4 v = *(const uint4*)(g_projT + (size_t)r * 2048 + jc * 256 + jt * 32 + q * 4);
            *(uint4*)(smem + SPT_OFF + r * 144 + q * 16) = v;
        }
#pragma unroll
        for (int h = 0; h < 4; h++) {
            uint2 bp0 = sBp[h * 512 + jt * 64 + 2 * p];
            uint2 bp1 = sBp[h * 512 + jt * 64 + 2 * p + 1];
            __nv_bfloat162 t0 = *(__nv_bfloat162*)&bp0.x;
            __nv_bfloat162 t0b = *(__nv_bfloat162*)&bp0.y;
            __nv_bfloat162 t1 = *(__nv_bfloat162*)&bp1.x;
            __nv_bfloat162 t1b = *(__nv_bfloat162*)&bp1.y;
            float thr0 = __low2float(t0), e10 = __high2float(t0), e20 = __low2float(t0b);
            float thr1 = __low2float(t1), e11 = __high2float(t1), e21 = __low2float(t1b);
#pragma unroll
            for (int s = 0; s < 8; s++) {
                float4 av = sAr[h * 64 + iseg * 8 + s];
                __nv_bfloat162 em2 = *(__nv_bfloat162*)&emv[s];
                float w0 = ((av.x > thr0) ? av.y * e10 : av.z * e20) * __low2float(em2);
                float w1 = ((av.x > thr1) ? av.y * e11 : av.z * e21) * __high2float(em2);
                sW[h * 2304 + (iseg * 8 + s) * 36 + p] = packbf2(w0, w1);
            }
        }
        // prefetch em for next tile (hidden under mma phase)
        if (jt < 7) {
#pragma unroll
            for (int s = 0; s < 8; s++) emv[s] = emrow[(size_t)s * (NN/2) + (jt + 1) * 32];
        }
        __syncthreads();

        // ---- mma phase: ldmatrix fragments + m16n8k16 ----
#pragma unroll
        for (int h = 0; h < 4; h++) {
            const uint32_t hA = aA + h * 9216;
            const uint32_t hB = aB + h * 9216;
#pragma unroll
            for (int kk = 0; kk < 4; kk++) {
                uint32_t a0, a1, a2, a3, b00, b01, b10, b11, b20, b21, b30, b31;
                ldsm4(a0, a1, a2, a3, hA + kk * 32);
                ldsm4(b00, b01, b10, b11, hB + kk * 32);
                ldsm4(b20, b21, b30, b31, hB + 16 * 144 + kk * 32);
                asm volatile(
                    "mma.sync.aligned.m16n8k16.row.col.f32.bf16.bf16.f32 "
                    "{%0,%1,%2,%3}, {%4,%5,%6,%7}, {%8,%9}, {%0,%1,%2,%3};"
                    : "+f"(acc[h][0][0]), "+f"(acc[h][0][1]), "+f"(acc[h][0][2]), "+f"(acc[h][0][3])
                    : "r"(a0), "r"(a1), "r"(a2), "r"(a3), "r"(b00), "r"(b01));
                asm volatile(
                    "mma.sync.aligned.m16n8k16.row.col.f32.bf16.bf16.f32 "
                    "{%0,%1,%2,%3}, {%4,%5,%6,%7}, {%8,%9}, {%0,%1,%2,%3};"
                    : "+f"(acc[h][1][0]), "+f"(acc[h][1][1]), "+f"(acc[h][1][2]), "+f"(acc[h][1][3])
                    : "r"(a0), "r"(a1), "r"(a2), "r"(a3), "r"(b10), "r"(b11));
                asm volatile(
                    "mma.sync.aligned.m16n8k16.row.col.f32.bf16.bf16.f32 "
                    "{%0,%1,%2,%3}, {%4,%5,%6,%7}, {%8,%9}, {%0,%1,%2,%3};"
                    : "+f"(acc[h][2][0]), "+f"(acc[h][2][1]), "+f"(acc[h][2][2]), "+f"(acc[h][2][3])
                    : "r"(a0), "r"(a1), "r"(a2), "r"(a3), "r"(b20), "r"(b21));
                asm volatile(
                    "mma.sync.aligned.m16n8k16.row.col.f32.bf16.bf16.f32 "
                    "{%0,%1,%2,%3}, {%4,%5,%6,%7}, {%8,%9}, {%0,%1,%2,%3};"
                    : "+f"(acc[h][3][0]), "+f"(acc[h][3][1]), "+f"(acc[h][3][2]), "+f"(acc[h][3][3])
                    : "r"(a0), "r"(a1), "r"(a2), "r"(a3), "r"(b30), "r"(b31));
            }
        }
        __syncthreads();   // all warps done reading sW/sPT before next overwrite
    }

    // ---- store partials ----
    float* pb = g_part + (size_t)jc * NN * 256;
#pragma unroll
    for (int h = 0; h < 4; h++)
#pragma unroll
        for (int nt = 0; nt < 4; nt++) {
            int col = h * 64 + ni + nt * 8 + 2 * tg;
            *(float2*)(pb + (size_t)(i0 + mi + g) * 256 + col) =
                make_float2(acc[h][nt][0], acc[h][nt][1]);
            *(float2*)(pb + (size_t)(i0 + mi + g + 8) * 256 + col) =
                make_float2(acc[h][nt][2], acc[h][nt][3]);
        }
}

// ---------------- K6: reduce partials + skip + ELU ----------------
__global__ void __launch_bounds__(256) k6_epilogue(float* __restrict__ out) {
    int gid = blockIdx.x * 256 + threadIdx.x;    // 262144 float4
    float4 s = make_float4(0.f, 0.f, 0.f, 0.f);
#pragma unroll
    for (int jc = 0; jc < 8; jc++) {
        float4 v = ((const float4*)(g_part + ((size_t)jc << 20)))[gid];
        s.x += v.x; s.y += v.y; s.z += v.z; s.w += v.w;
    }
    int i = gid >> 6, c = (gid & 63) * 4;
    float4 sk = *(const float4*)(g_hidden + (size_t)i * CC + 256 + c);
    float x0 = s.x + sk.x, x1 = s.y + sk.y, x2 = s.z + sk.z, x3 = s.w + sk.w;
    x0 = x0 > 0.f ? x0 : (__expf(x0) - 1.f);
    x1 = x1 > 0.f ? x1 : (__expf(x1) - 1.f);
    x2 = x2 > 0.f ? x2 : (__expf(x2) - 1.f);
    x3 = x3 > 0.f ? x3 : (__expf(x3) - 1.f);
    ((float4*)out)[gid] = make_float4(x0, x1, x2, x3);
}

// ---------------- launcher ----------------
extern "C" void kernel_launch(void* const* d_in, const int* in_sizes, int n_in,
                              void* d_out, int out_size) {
    const float* nodes = (const float*)d_in[0];
    const float* degm  = (const float*)d_in[1];
    // d_in[2] = edges_features_distance (unused by reference)
    const float* bond  = (const float*)d_in[3];
    const float* projp = (const float*)d_in[4];
    const float* ssrc  = (const float*)d_in[5];
    const float* stgt  = (const float*)d_in[6];
    const float* skw   = (const float*)d_in[7];
    const float* cutp  = (const float*)d_in[8];
    float* out = (float*)d_out;

    k0_weights<<<256, 256>>>(projp, skw);
    k1_gemm<<<dim3(128, 8), 256>>>(nodes);
    k1b_transpose<<<dim3(64, 4), 256>>>();
    k2_scores<<<2048, 256>>>(ssrc, stgt);
    k3_mask<<<4096, 256>>>(degm, bond, cutp, out + (size_t)NN * 256);
    k5_colsum<<<128, 256>>>();
    k1d_bp<<<64, 256>>>();

    cudaFuncSetAttribute(k4_mma, cudaFuncAttributeMaxDynamicSharedMemorySize, SM4_TOT);
    k4_mma<<<dim3(64, 8), 256, SM4_TOT>>>();
    k6_epilogue<<<1024, 256>>>(out);
}

// round 10
// speedup vs baseline: 4.6845x; 1.4457x over previous
#include <cuda_runtime.h>
#include <cuda_bf16.h>
#include <cuda_fp16.h>
#include <cstdint>

#define NN 4096
#define FIN 128
#define FO 64
#define HH 4
#define CC 512   // 256 proj cols (h*64+o) + 256 skip cols

// ---------------- scratch (static device globals; no allocation) ----------------
__device__ uint32_t g_em[(size_t)NN * NN / 2];     // exp(mask) bf16 pairs (32 MB)
__device__ float    g_hidden[(size_t)NN * CC];     // [n][c]: c<256 proj, c>=256 skip (8 MB)
__device__ float    g_Wc[FIN * CC];                // combined weights [f][c]
__device__ float4   g_A[HH * NN];                  // per (h,i): a, e^a, e^{0.2a}, -
__device__ float4   g_B[HH * NN];                  // per (h,j): b, e^b, e^{0.2b}, -
__device__ uint32_t g_projT[(size_t)256 * (NN/2)]; // projT fp16 pairs: row c=h*64+f, cols j (2 MB)
__device__ uint2    g_Bp[HH * NN];                 // packed bf16 (thr,e1),(e2,0) per (h,j)
__device__ float    g_Zp[4][2][HH * NN];           // k5 row-chunk partial column sums (512 KB)
__device__ float    g_part[(size_t)8 * NN * 256];  // per-j-chunk partial outputs (32 MB)

// ---------------- helpers ----------------
__device__ __forceinline__ float maskf(float d, float b, float cut) {
    float wdm = d + b;
    return wdm > 0.f ? wdm : (b > cut ? (b + wdm) : -1e9f);
}
__device__ __forceinline__ uint32_t packbf2(float lo, float hi) {
    __nv_bfloat162 p = __floats2bfloat162_rn(lo, hi);
    return *(uint32_t*)&p;
}
__device__ __forceinline__ uint32_t packh2(float lo, float hi) {
    __half2 p = __floats2half2_rn(lo, hi);
    return *(uint32_t*)&p;
}
__device__ __forceinline__ uint32_t smem_u32(const void* p) {
    uint32_t a;
    asm("{ .reg .u64 t; cvta.to.shared.u64 t, %1; cvt.u32.u64 %0, t; }" : "=r"(a) : "l"(p));
    return a;
}
__device__ __forceinline__ void ldsm4(uint32_t& r0, uint32_t& r1, uint32_t& r2, uint32_t& r3,
                                      uint32_t addr) {
    asm volatile("ldmatrix.sync.aligned.m8n8.x4.shared.b16 {%0,%1,%2,%3}, [%4];"
                 : "=r"(r0), "=r"(r1), "=r"(r2), "=r"(r3) : "r"(addr));
}

// ---------------- K0: build combined weight matrix Wc[f][c] ----------------
__global__ void k0_weights(const float* __restrict__ projp, const float* __restrict__ skw) {
    int idx = blockIdx.x * 256 + threadIdx.x;
    int f = idx >> 9, c = idx & 511;
    float v;
    if (c < 256) v = projp[(c >> 6) * (FIN * FO) + f * FO + (c & 63)];
    else         v = skw[(c - 256) * FIN + f];
    g_Wc[idx] = v;
}

// ---------------- K1: hidden = nodes[4096,128] @ Wc[128,512] ----------------
__global__ void __launch_bounds__(256) k1_gemm(const float* __restrict__ nodes) {
    __shared__ float sN[32 * 128];
    __shared__ float sW[128 * 64];
    const int t = threadIdx.x;
    const int i0 = blockIdx.x * 32;
    const int c0 = blockIdx.y * 64;
#pragma unroll
    for (int k = 0; k < 4; k++) {
        int q = t + k * 256;
        ((float4*)sN)[q] = ((const float4*)(nodes + (size_t)i0 * FIN))[q];
    }
#pragma unroll
    for (int k = 0; k < 8; k++) {
        int idx = t + k * 256;
        int f = idx >> 4, q = idx & 15;
        *(float4*)(sW + f * 64 + q * 4) = *(const float4*)(g_Wc + f * CC + c0 + q * 4);
    }
    __syncthreads();
    const int c = t & 63, rg = t >> 6;
    float acc[8] = {0.f,0.f,0.f,0.f,0.f,0.f,0.f,0.f};
#pragma unroll 4
    for (int f = 0; f < 128; f++) {
        float wv = sW[f * 64 + c];
#pragma unroll
        for (int r = 0; r < 8; r++)
            acc[r] += sN[(rg * 8 + r) * 128 + f] * wv;
    }
#pragma unroll
    for (int r = 0; r < 8; r++)
        g_hidden[(size_t)(i0 + rg * 8 + r) * CC + c0 + c] = acc[r];
}

// ---------------- K1b: transpose proj -> g_projT fp16 [c][j] ----------------
__global__ void __launch_bounds__(256) k1b_transpose() {
    __shared__ float sT[64 * 65];
    const int t = threadIdx.x;
    const int j0 = blockIdx.x * 64;
    const int c0 = blockIdx.y * 64;
#pragma unroll
    for (int k = 0; k < 4; k++) {
        int idx = t + k * 256;
        int jr = idx >> 4, q = idx & 15;
        float4 v = *(const float4*)(g_hidden + (size_t)(j0 + jr) * CC + c0 + q * 4);
        sT[(q * 4 + 0) * 65 + jr] = v.x;
        sT[(q * 4 + 1) * 65 + jr] = v.y;
        sT[(q * 4 + 2) * 65 + jr] = v.z;
        sT[(q * 4 + 3) * 65 + jr] = v.w;
    }
    __syncthreads();
#pragma unroll
    for (int k = 0; k < 8; k++) {
        int idx = t + k * 256;
        int cr = idx >> 5, p = idx & 31;
        g_projT[(size_t)(c0 + cr) * (NN/2) + (j0 >> 1) + p] =
            packh2(sT[cr * 65 + 2 * p], sT[cr * 65 + 2 * p + 1]);
    }
}

// ---------------- K1d: finalize Z from k5 partials, pack softmax B-params ----------------
__global__ void k1d_bp() {
    int idx = blockIdx.x * 256 + threadIdx.x;   // 16384
    float4 Bv = g_B[idx];
    float z1 = g_Zp[0][0][idx] + g_Zp[1][0][idx] + g_Zp[2][0][idx] + g_Zp[3][0][idx];
    float z2 = g_Zp[0][1][idx] + g_Zp[1][1][idx] + g_Zp[2][1][idx] + g_Zp[3][1][idx];
    float inv = 1.0f / (Bv.y * z1 + Bv.z * z2);
    g_Bp[idx] = make_uint2(packbf2(-Bv.x, Bv.y * inv), packbf2(Bv.z * inv, 0.f));
}

// ---------------- K2: per-(h,n) scores a,b and their exponentials ----------------
__global__ void __launch_bounds__(256) k2_scores(const float* __restrict__ ssrc,
                                                 const float* __restrict__ stgt) {
    int w = blockIdx.x * 8 + (threadIdx.x >> 5);
    int lane = threadIdx.x & 31;
    int h = w >> 12, n = w & (NN - 1);
    const float* pr = g_hidden + (size_t)n * CC + h * FO;
    float p0 = pr[lane], p1 = pr[lane + 32];
    float sa = p0 * ssrc[h * FO + lane] + p1 * ssrc[h * FO + lane + 32];
    float sb = p0 * stgt[h * FO + lane] + p1 * stgt[h * FO + lane + 32];
#pragma unroll
    for (int o = 16; o > 0; o >>= 1) {
        sa += __shfl_xor_sync(0xffffffffu, sa, o);
        sb += __shfl_xor_sync(0xffffffffu, sb, o);
    }
    if (lane == 0) {
        g_A[h * NN + n] = make_float4(sa, __expf(sa), __expf(0.2f * sa), 0.f);
        g_B[h * NN + n] = make_float4(sb, __expf(sb), __expf(0.2f * sb), 0.f);
    }
}

// ---------------- K3: mask -> emask(bf16) + LayerNorm(mask) ----------------
__global__ void __launch_bounds__(256) k3_mask(const float* __restrict__ deg,
                                               const float* __restrict__ bond,
                                               const float* __restrict__ cutp,
                                               float* __restrict__ out_ln) {
    __shared__ float srow[NN];
    __shared__ float red1[256], red2[256];
    const int i = blockIdx.x;
    const int t = threadIdx.x;
    const float cut = cutp[0];
    const float4* d4 = (const float4*)(deg  + (size_t)i * NN);
    const float4* b4 = (const float4*)(bond + (size_t)i * NN);
    uint2* e2 = (uint2*)(g_em + (size_t)i * (NN/2));
    float s = 0.f, sq = 0.f;
#pragma unroll
    for (int k = 0; k < 4; k++) {
        int q = t + k * 256;
        float4 dv = d4[q], bv = b4[q];
        float4 mv;
        mv.x = maskf(dv.x, bv.x, cut);
        mv.y = maskf(dv.y, bv.y, cut);
        mv.z = maskf(dv.z, bv.z, cut);
        mv.w = maskf(dv.w, bv.w, cut);
        ((float4*)srow)[q] = mv;
        uint2 ev;
        ev.x = packbf2(__expf(mv.x), __expf(mv.y));
        ev.y = packbf2(__expf(mv.z), __expf(mv.w));
        e2[q] = ev;
        s  += (mv.x + mv.y) + (mv.z + mv.w);
        sq += mv.x * mv.x + mv.y * mv.y + mv.z * mv.z + mv.w * mv.w;
    }
    red1[t] = s; red2[t] = sq;
    __syncthreads();
    for (int o = 128; o > 0; o >>= 1) {
        if (t < o) { red1[t] += red1[t + o]; red2[t] += red2[t + o]; }
        __syncthreads();
    }
    float mu  = red1[0] * (1.f / NN);
    float var = red2[0] * (1.f / NN) - mu * mu;
    float rs  = rsqrtf(var + 1e-5f);
    float4* o4 = (float4*)(out_ln + (size_t)i * NN);
#pragma unroll
    for (int k = 0; k < 4; k++) {
        int q = t + k * 256;
        float4 mv = ((float4*)srow)[q];
        o4[q] = make_float4((mv.x - mu) * rs, (mv.y - mu) * rs,
                            (mv.z - mu) * rs, (mv.w - mu) * rs);
    }
}

// ---------------- K5: partial column sums over 1024-row chunks ----------------
// grid (128 j-blocks of 32, 4 row-chunks). Partials to g_Zp[chunk]; k1d finalizes.
__global__ void __launch_bounds__(256) k5_colsum() {
    __shared__ float4 sA[4 * 256];
    __shared__ float sS1[4 * 8 * 32];
    __shared__ float sS2[4 * 8 * 32];
    const int t = threadIdx.x;
    const int j0 = blockIdx.x * 32;
    const int cb = blockIdx.y;            // row chunk: rows cb*1024 .. +1024
    const int col = t & 31, seg = t >> 5;
    const int j = j0 + col;
    const __nv_bfloat16* emb = (const __nv_bfloat16*)g_em;
    float thr[4];
#pragma unroll
    for (int h = 0; h < 4; h++) thr[h] = -g_B[h * NN + j].x;
    float S1[4] = {0,0,0,0}, S2[4] = {0,0,0,0};
    for (int c0 = cb * 1024; c0 < cb * 1024 + 1024; c0 += 256) {
        __syncthreads();
#pragma unroll
        for (int k = 0; k < 4; k++) {
            int idx = t + k * 256;
            sA[idx] = g_A[(idx >> 8) * NN + c0 + (idx & 255)];
        }
        __syncthreads();
        const __nv_bfloat16* emp = emb + (size_t)(c0 + seg * 32) * NN + j;
#pragma unroll 8
        for (int s = 0; s < 32; s++) {
            float em = __bfloat162float(emp[(size_t)s * NN]);
#pragma unroll
            for (int h = 0; h < 4; h++) {
                float4 av = sA[h * 256 + seg * 32 + s];
                if (av.x > thr[h]) S1[h] += av.y * em; else S2[h] += av.z * em;
            }
        }
    }
#pragma unroll
    for (int h = 0; h < 4; h++) {
        sS1[(h * 8 + seg) * 32 + col] = S1[h];
        sS2[(h * 8 + seg) * 32 + col] = S2[h];
    }
    __syncthreads();
    if (t < 128) {
        int h = t >> 5, c = t & 31;
        float z1 = 0.f, z2 = 0.f;
#pragma unroll
        for (int s = 0; s < 8; s++) { z1 += sS1[(h * 8 + s) * 32 + c]; z2 += sS2[(h * 8 + s) * 32 + c]; }
        g_Zp[cb][0][h * NN + j0 + c] = z1;
        g_Zp[cb][1][h * NN + j0 + c] = z2;
    }
}

// ---------------- K4: attn @ proj (4 heads) via fp16 m16n8k16 + ldmatrix ----------------
// Grid (64 i-tiles of 64, 8 j-chunks of 512), 256 threads. smem layout (bytes):
//   sW  [4][64 rows][36 u32]  @ 0       (attention weights, fp16, stride 144B)
//   sPT [256 rows c][36 u32]  @ 36864   (projT tile, fp16, rows c = h*64+f)
//   sBp [4][512] uint2        @ 73728   (bf16 thr,e1,e2 per (h,j) of this chunk)
//   sAr [4][64] float4        @ 90112   (a, e^a, e^{0.2a} per (h,i))
#define SW_OFF  0
#define SPT_OFF 36864
#define SBP_OFF 73728
#define SAR_OFF 90112
#define SM4_TOT 94208
__global__ void __launch_bounds__(256) k4_mma() {
    extern __shared__ char smem[];
    const uint32_t smb = smem_u32(smem);
    uint32_t* sW  = (uint32_t*)(smem + SW_OFF);
    uint2*    sBp = (uint2*)(smem + SBP_OFF);
    float4*   sAr = (float4*)(smem + SAR_OFF);
    const int t = threadIdx.x;
    const int i0 = blockIdx.x * 64;
    const int jc = blockIdx.y;
    const int lane = t & 31, w = t >> 5;
    const int g = lane >> 2, tg = lane & 3;
    const int mi = (w & 3) * 16, ni = (w >> 2) * 32;
    const int p = lane;     // j-pair 0..31 (w-gen)
    const int iseg = w;     // warp -> rows iseg*8..+8 (w-gen)

    // ---- prologue: stage sAr, sBp ----
    sAr[t] = g_A[(t >> 6) * NN + i0 + (t & 63)];
#pragma unroll
    for (int k = 0; k < 8; k++) {
        int idx = t + k * 256;
        sBp[idx] = g_Bp[(idx >> 9) * NN + jc * 512 + (idx & 511)];
    }
    float acc[4][4][4];
#pragma unroll
    for (int h = 0; h < 4; h++)
#pragma unroll
        for (int n = 0; n < 4; n++)
#pragma unroll
            for (int r = 0; r < 4; r++) acc[h][n][r] = 0.f;

    // ldmatrix lane address offsets (bytes)
    const uint32_t aA  = smb + SW_OFF + (mi + (lane & 15)) * 144 + (lane >> 4) * 16;
    const uint32_t aB  = smb + SPT_OFF +
                         (ni + ((lane >> 4) & 1) * 8 + (lane & 7)) * 144 +
                         ((lane >> 3) & 1) * 16;
    const uint32_t* emrow = g_em + (size_t)(i0 + iseg * 8) * (NN/2) + jc * 256 + p;

    // prefetch em for tile 0
    uint32_t emv[8];
#pragma unroll
    for (int s = 0; s < 8; s++) emv[s] = emrow[(size_t)s * (NN/2)];
    __syncthreads();

    for (int jt = 0; jt < 8; jt++) {
        // ---- stage projT tile (L2-hot) + compute w -> sW ----
#pragma unroll
        for (int k = 0; k < 8; k++) {
            int idx = t + k * 256;
            int r = idx >> 3, q = idx & 7;
            uint4 v = *(const uint4*)(g_projT + (size_t)r * 2048 + jc * 256 + jt * 32 + q * 4);
            *(uint4*)(smem + SPT_OFF + r * 144 + q * 16) = v;
        }
#pragma unroll
        for (int h = 0; h < 4; h++) {
            uint2 bp0 = sBp[h * 512 + jt * 64 + 2 * p];
            uint2 bp1 = sBp[h * 512 + jt * 64 + 2 * p + 1];
            __nv_bfloat162 t0 = *(__nv_bfloat162*)&bp0.x;
            __nv_bfloat162 t0b = *(__nv_bfloat162*)&bp0.y;
            __nv_bfloat162 t1 = *(__nv_bfloat162*)&bp1.x;
            __nv_bfloat162 t1b = *(__nv_bfloat162*)&bp1.y;
            float thr0 = __low2float(t0), e10 = __high2float(t0), e20 = __low2float(t0b);
            float thr1 = __low2float(t1), e11 = __high2float(t1), e21 = __low2float(t1b);
#pragma unroll
            for (int s = 0; s < 8; s++) {
                float4 av = sAr[h * 64 + iseg * 8 + s];
                __nv_bfloat162 em2 = *(__nv_bfloat162*)&emv[s];
                float w0 = ((av.x > thr0) ? av.y * e10 : av.z * e20) * __low2float(em2);
                float w1 = ((av.x > thr1) ? av.y * e11 : av.z * e21) * __high2float(em2);
                sW[h * 2304 + (iseg * 8 + s) * 36 + p] = packh2(w0, w1);
            }
        }
        // prefetch em for next tile (hidden under mma phase)
        if (jt < 7) {
#pragma unroll
            for (int s = 0; s < 8; s++) emv[s] = emrow[(size_t)s * (NN/2) + (jt + 1) * 32];
        }
        __syncthreads();

        // ---- mma phase: ldmatrix fragments + m16n8k16 fp16 ----
#pragma unroll
        for (int h = 0; h < 4; h++) {
            const uint32_t hA = aA + h * 9216;
            const uint32_t hB = aB + h * 9216;
#pragma unroll
            for (int kk = 0; kk < 4; kk++) {
                uint32_t a0, a1, a2, a3, b00, b01, b10, b11, b20, b21, b30, b31;
                ldsm4(a0, a1, a2, a3, hA + kk * 32);
                ldsm4(b00, b01, b10, b11, hB + kk * 32);
                ldsm4(b20, b21, b30, b31, hB + 16 * 144 + kk * 32);
                asm volatile(
                    "mma.sync.aligned.m16n8k16.row.col.f32.f16.f16.f32 "
                    "{%0,%1,%2,%3}, {%4,%5,%6,%7}, {%8,%9}, {%0,%1,%2,%3};"
                    : "+f"(acc[h][0][0]), "+f"(acc[h][0][1]), "+f"(acc[h][0][2]), "+f"(acc[h][0][3])
                    : "r"(a0), "r"(a1), "r"(a2), "r"(a3), "r"(b00), "r"(b01));
                asm volatile(
                    "mma.sync.aligned.m16n8k16.row.col.f32.f16.f16.f32 "
                    "{%0,%1,%2,%3}, {%4,%5,%6,%7}, {%8,%9}, {%0,%1,%2,%3};"
                    : "+f"(acc[h][1][0]), "+f"(acc[h][1][1]), "+f"(acc[h][1][2]), "+f"(acc[h][1][3])
                    : "r"(a0), "r"(a1), "r"(a2), "r"(a3), "r"(b10), "r"(b11));
                asm volatile(
                    "mma.sync.aligned.m16n8k16.row.col.f32.f16.f16.f32 "
                    "{%0,%1,%2,%3}, {%4,%5,%6,%7}, {%8,%9}, {%0,%1,%2,%3};"
                    : "+f"(acc[h][2][0]), "+f"(acc[h][2][1]), "+f"(acc[h][2][2]), "+f"(acc[h][2][3])
                    : "r"(a0), "r"(a1), "r"(a2), "r"(a3), "r"(b20), "r"(b21));
                asm volatile(
                    "mma.sync.aligned.m16n8k16.row.col.f32.f16.f16.f32 "
                    "{%0,%1,%2,%3}, {%4,%5,%6,%7}, {%8,%9}, {%0,%1,%2,%3};"
                    : "+f"(acc[h][3][0]), "+f"(acc[h][3][1]), "+f"(acc[h][3][2]), "+f"(acc[h][3][3])
                    : "r"(a0), "r"(a1), "r"(a2), "r"(a3), "r"(b30), "r"(b31));
            }
        }
        __syncthreads();   // all warps done reading sW/sPT before next overwrite
    }

    // ---- store partials ----
    float* pb = g_part + (size_t)jc * NN * 256;
#pragma unroll
    for (int h = 0; h < 4; h++)
#pragma unroll
        for (int nt = 0; nt < 4; nt++) {
            int col = h * 64 + ni + nt * 8 + 2 * tg;
            *(float2*)(pb + (size_t)(i0 + mi + g) * 256 + col) =
                make_float2(acc[h][nt][0], acc[h][nt][1]);
            *(float2*)(pb + (size_t)(i0 + mi + g + 8) * 256 + col) =
                make_float2(acc[h][nt][2], acc[h][nt][3]);
        }
}

// ---------------- K6: reduce partials + skip + ELU ----------------
__global__ void __launch_bounds__(256) k6_epilogue(float* __restrict__ out) {
    int gid = blockIdx.x * 256 + threadIdx.x;    // 262144 float4
    float4 s = make_float4(0.f, 0.f, 0.f, 0.f);
#pragma unroll
    for (int jc = 0; jc < 8; jc++) {
        float4 v = ((const float4*)(g_part + ((size_t)jc << 20)))[gid];
        s.x += v.x; s.y += v.y; s.z += v.z; s.w += v.w;
    }
    int i = gid >> 6, c = (gid & 63) * 4;
    float4 sk = *(const float4*)(g_hidden + (size_t)i * CC + 256 + c);
    float x0 = s.x + sk.x, x1 = s.y + sk.y, x2 = s.z + sk.z, x3 = s.w + sk.w;
    x0 = x0 > 0.f ? x0 : (__expf(x0) - 1.f);
    x1 = x1 > 0.f ? x1 : (__expf(x1) - 1.f);
    x2 = x2 > 0.f ? x2 : (__expf(x2) - 1.f);
    x3 = x3 > 0.f ? x3 : (__expf(x3) - 1.f);
    ((float4*)out)[gid] = make_float4(x0, x1, x2, x3);
}

// ---------------- launcher ----------------
extern "C" void kernel_launch(void* const* d_in, const int* in_sizes, int n_in,
                              void* d_out, int out_size) {
    const float* nodes = (const float*)d_in[0];
    const float* degm  = (const float*)d_in[1];
    // d_in[2] = edges_features_distance (unused by reference)
    const float* bond  = (const float*)d_in[3];
    const float* projp = (const float*)d_in[4];
    const float* ssrc  = (const float*)d_in[5];
    const float* stgt  = (const float*)d_in[6];
    const float* skw   = (const float*)d_in[7];
    const float* cutp  = (const float*)d_in[8];
    float* out = (float*)d_out;

    k0_weights<<<256, 256>>>(projp, skw);
    k1_gemm<<<dim3(128, 8), 256>>>(nodes);
    k1b_transpose<<<dim3(64, 4), 256>>>();
    k2_scores<<<2048, 256>>>(ssrc, stgt);
    k3_mask<<<4096, 256>>>(degm, bond, cutp, out + (size_t)NN * 256);
    k5_colsum<<<dim3(128, 4), 256>>>();
    k1d_bp<<<64, 256>>>();

    cudaFuncSetAttribute(k4_mma, cudaFuncAttributeMaxDynamicSharedMemorySize, SM4_TOT);
    k4_mma<<<dim3(64, 8), 256, SM4_TOT>>>();
    k6_epilogue<<<1024, 256>>>(out);
}

// round 11
// speedup vs baseline: 4.8775x; 1.0412x over previous
#include <cuda_runtime.h>
#include <cuda_bf16.h>
#include <cuda_fp16.h>
#include <cstdint>

#define NN 4096
#define FIN 128
#define FO 64
#define HH 4
#define CC 512   // 256 proj cols (h*64+o) + 256 skip cols

// ---------------- scratch (static device globals; no allocation) ----------------
__device__ uint32_t g_em[(size_t)NN * NN / 2];     // exp(mask) bf16 pairs (32 MB)
__device__ float    g_hidden[(size_t)NN * CC];     // [n][c]: c<256 proj, c>=256 skip (8 MB)
__device__ float    g_Wc[FIN * CC];                // combined weights [f][c]
__device__ float4   g_A[HH * NN];                  // per (h,i): a, e^a, e^{0.2a}, -
__device__ float4   g_B[HH * NN];                  // per (h,j): b, e^b, e^{0.2b}, -
__device__ uint32_t g_projT[(size_t)256 * (NN/2)]; // projT fp16 pairs: row c=h*64+f, cols j (2 MB)
__device__ uint2    g_Bp[HH * NN];                 // packed bf16 (thr,e1),(e2,0) per (h,j)
__device__ float    g_Zp[4][2][HH * NN];           // k5 row-chunk partial column sums (512 KB)
__device__ float    g_part[(size_t)4 * NN * 256];  // per-j-chunk partial outputs (16 MB)

// ---------------- helpers ----------------
__device__ __forceinline__ float maskf(float d, float b, float cut) {
    float wdm = d + b;
    return wdm > 0.f ? wdm : (b > cut ? (b + wdm) : -1e9f);
}
__device__ __forceinline__ uint32_t packbf2(float lo, float hi) {
    __nv_bfloat162 p = __floats2bfloat162_rn(lo, hi);
    return *(uint32_t*)&p;
}
__device__ __forceinline__ uint32_t packh2(float lo, float hi) {
    __half2 p = __floats2half2_rn(lo, hi);
    return *(uint32_t*)&p;
}
__device__ __forceinline__ uint32_t smem_u32(const void* p) {
    uint32_t a;
    asm("{ .reg .u64 t; cvta.to.shared.u64 t, %1; cvt.u32.u64 %0, t; }" : "=r"(a) : "l"(p));
    return a;
}
__device__ __forceinline__ void ldsm4(uint32_t& r0, uint32_t& r1, uint32_t& r2, uint32_t& r3,
                                      uint32_t addr) {
    asm volatile("ldmatrix.sync.aligned.m8n8.x4.shared.b16 {%0,%1,%2,%3}, [%4];"
                 : "=r"(r0), "=r"(r1), "=r"(r2), "=r"(r3) : "r"(addr));
}
__device__ __forceinline__ void cpasync16(uint32_t saddr, const void* gaddr) {
    asm volatile("cp.async.cg.shared.global [%0], [%1], 16;" :: "r"(saddr), "l"(gaddr));
}

// ---------------- K0: build combined weight matrix Wc[f][c] ----------------
__global__ void k0_weights(const float* __restrict__ projp, const float* __restrict__ skw) {
    int idx = blockIdx.x * 256 + threadIdx.x;
    int f = idx >> 9, c = idx & 511;
    float v;
    if (c < 256) v = projp[(c >> 6) * (FIN * FO) + f * FO + (c & 63)];
    else         v = skw[(c - 256) * FIN + f];
    g_Wc[idx] = v;
}

// ---------------- K1: hidden = nodes[4096,128] @ Wc[128,512] ----------------
__global__ void __launch_bounds__(256) k1_gemm(const float* __restrict__ nodes) {
    __shared__ float sN[32 * 128];
    __shared__ float sW[128 * 64];
    const int t = threadIdx.x;
    const int i0 = blockIdx.x * 32;
    const int c0 = blockIdx.y * 64;
#pragma unroll
    for (int k = 0; k < 4; k++) {
        int q = t + k * 256;
        ((float4*)sN)[q] = ((const float4*)(nodes + (size_t)i0 * FIN))[q];
    }
#pragma unroll
    for (int k = 0; k < 8; k++) {
        int idx = t + k * 256;
        int f = idx >> 4, q = idx & 15;
        *(float4*)(sW + f * 64 + q * 4) = *(const float4*)(g_Wc + f * CC + c0 + q * 4);
    }
    __syncthreads();
    const int c = t & 63, rg = t >> 6;
    float acc[8] = {0.f,0.f,0.f,0.f,0.f,0.f,0.f,0.f};
#pragma unroll 4
    for (int f = 0; f < 128; f++) {
        float wv = sW[f * 64 + c];
#pragma unroll
        for (int r = 0; r < 8; r++)
            acc[r] += sN[(rg * 8 + r) * 128 + f] * wv;
    }
#pragma unroll
    for (int r = 0; r < 8; r++)
        g_hidden[(size_t)(i0 + rg * 8 + r) * CC + c0 + c] = acc[r];
}

// ---------------- K1b: transpose proj -> g_projT fp16 [c][j] ----------------
__global__ void __launch_bounds__(256) k1b_transpose() {
    __shared__ float sT[64 * 65];
    const int t = threadIdx.x;
    const int j0 = blockIdx.x * 64;
    const int c0 = blockIdx.y * 64;
#pragma unroll
    for (int k = 0; k < 4; k++) {
        int idx = t + k * 256;
        int jr = idx >> 4, q = idx & 15;
        float4 v = *(const float4*)(g_hidden + (size_t)(j0 + jr) * CC + c0 + q * 4);
        sT[(q * 4 + 0) * 65 + jr] = v.x;
        sT[(q * 4 + 1) * 65 + jr] = v.y;
        sT[(q * 4 + 2) * 65 + jr] = v.z;
        sT[(q * 4 + 3) * 65 + jr] = v.w;
    }
    __syncthreads();
#pragma unroll
    for (int k = 0; k < 8; k++) {
        int idx = t + k * 256;
        int cr = idx >> 5, p = idx & 31;
        g_projT[(size_t)(c0 + cr) * (NN/2) + (j0 >> 1) + p] =
            packh2(sT[cr * 65 + 2 * p], sT[cr * 65 + 2 * p + 1]);
    }
}

// ---------------- K1d: finalize Z from k5 partials, pack softmax B-params ----------------
__global__ void k1d_bp() {
    int idx = blockIdx.x * 256 + threadIdx.x;   // 16384
    float4 Bv = g_B[idx];
    float z1 = g_Zp[0][0][idx] + g_Zp[1][0][idx] + g_Zp[2][0][idx] + g_Zp[3][0][idx];
    float z2 = g_Zp[0][1][idx] + g_Zp[1][1][idx] + g_Zp[2][1][idx] + g_Zp[3][1][idx];
    float inv = 1.0f / (Bv.y * z1 + Bv.z * z2);
    g_Bp[idx] = make_uint2(packbf2(-Bv.x, Bv.y * inv), packbf2(Bv.z * inv, 0.f));
}

// ---------------- K2: per-(h,n) scores; 2 nodes per warp for MLP ----------------
__global__ void __launch_bounds__(256) k2_scores(const float* __restrict__ ssrc,
                                                 const float* __restrict__ stgt) {
    int w = blockIdx.x * 8 + (threadIdx.x >> 5);    // 0..8191
    int lane = threadIdx.x & 31;
    int h = w >> 11, n = w & 2047;
    float ss0 = ssrc[h * FO + lane], ss1 = ssrc[h * FO + lane + 32];
    float st0 = stgt[h * FO + lane], st1 = stgt[h * FO + lane + 32];
    const float* prA = g_hidden + (size_t)n * CC + h * FO;
    const float* prB = g_hidden + (size_t)(n + 2048) * CC + h * FO;
    float a0 = prA[lane], a1 = prA[lane + 32];
    float b0 = prB[lane], b1 = prB[lane + 32];
    float saA = a0 * ss0 + a1 * ss1, sbA = a0 * st0 + a1 * st1;
    float saB = b0 * ss0 + b1 * ss1, sbB = b0 * st0 + b1 * st1;
#pragma unroll
    for (int o = 16; o > 0; o >>= 1) {
        saA += __shfl_xor_sync(0xffffffffu, saA, o);
        sbA += __shfl_xor_sync(0xffffffffu, sbA, o);
        saB += __shfl_xor_sync(0xffffffffu, saB, o);
        sbB += __shfl_xor_sync(0xffffffffu, sbB, o);
    }
    if (lane == 0) {
        g_A[h * NN + n] = make_float4(saA, __expf(saA), __expf(0.2f * saA), 0.f);
        g_B[h * NN + n] = make_float4(sbA, __expf(sbA), __expf(0.2f * sbA), 0.f);
        g_A[h * NN + n + 2048] = make_float4(saB, __expf(saB), __expf(0.2f * saB), 0.f);
        g_B[h * NN + n + 2048] = make_float4(sbB, __expf(sbB), __expf(0.2f * sbB), 0.f);
    }
}

// ---------------- K3: mask -> emask(bf16) + LayerNorm(mask), 512 threads ----------------
__global__ void __launch_bounds__(512) k3_mask(const float* __restrict__ deg,
                                               const float* __restrict__ bond,
                                               const float* __restrict__ cutp,
                                               float* __restrict__ out_ln) {
    __shared__ float srow[NN];
    __shared__ float red1[512], red2[512];
    const int i = blockIdx.x;
    const int t = threadIdx.x;
    const float cut = cutp[0];
    const float4* d4 = (const float4*)(deg  + (size_t)i * NN);
    const float4* b4 = (const float4*)(bond + (size_t)i * NN);
    uint2* e2 = (uint2*)(g_em + (size_t)i * (NN/2));
    float s = 0.f, sq = 0.f;
#pragma unroll
    for (int k = 0; k < 2; k++) {
        int q = t + k * 512;
        float4 dv = d4[q], bv = b4[q];
        float4 mv;
        mv.x = maskf(dv.x, bv.x, cut);
        mv.y = maskf(dv.y, bv.y, cut);
        mv.z = maskf(dv.z, bv.z, cut);
        mv.w = maskf(dv.w, bv.w, cut);
        ((float4*)srow)[q] = mv;
        uint2 ev;
        ev.x = packbf2(__expf(mv.x), __expf(mv.y));
        ev.y = packbf2(__expf(mv.z), __expf(mv.w));
        e2[q] = ev;
        s  += (mv.x + mv.y) + (mv.z + mv.w);
        sq += mv.x * mv.x + mv.y * mv.y + mv.z * mv.z + mv.w * mv.w;
    }
    red1[t] = s; red2[t] = sq;
    __syncthreads();
    for (int o = 256; o > 0; o >>= 1) {
        if (t < o) { red1[t] += red1[t + o]; red2[t] += red2[t + o]; }
        __syncthreads();
    }
    float mu  = red1[0] * (1.f / NN);
    float var = red2[0] * (1.f / NN) - mu * mu;
    float rs  = rsqrtf(var + 1e-5f);
    float4* o4 = (float4*)(out_ln + (size_t)i * NN);
#pragma unroll
    for (int k = 0; k < 2; k++) {
        int q = t + k * 512;
        float4 mv = ((float4*)srow)[q];
        o4[q] = make_float4((mv.x - mu) * rs, (mv.y - mu) * rs,
                            (mv.z - mu) * rs, (mv.w - mu) * rs);
    }
}

// ---------------- K5: partial column sums over 1024-row chunks ----------------
__global__ void __launch_bounds__(256) k5_colsum() {
    __shared__ float4 sA[4 * 256];
    __shared__ float sS1[4 * 8 * 32];
    __shared__ float sS2[4 * 8 * 32];
    const int t = threadIdx.x;
    const int j0 = blockIdx.x * 32;
    const int cb = blockIdx.y;
    const int col = t & 31, seg = t >> 5;
    const int j = j0 + col;
    const __nv_bfloat16* emb = (const __nv_bfloat16*)g_em;
    float thr[4];
#pragma unroll
    for (int h = 0; h < 4; h++) thr[h] = -g_B[h * NN + j].x;
    float S1[4] = {0,0,0,0}, S2[4] = {0,0,0,0};
    for (int c0 = cb * 1024; c0 < cb * 1024 + 1024; c0 += 256) {
        __syncthreads();
#pragma unroll
        for (int k = 0; k < 4; k++) {
            int idx = t + k * 256;
            sA[idx] = g_A[(idx >> 8) * NN + c0 + (idx & 255)];
        }
        __syncthreads();
        const __nv_bfloat16* emp = emb + (size_t)(c0 + seg * 32) * NN + j;
#pragma unroll 8
        for (int s = 0; s < 32; s++) {
            float em = __bfloat162float(emp[(size_t)s * NN]);
#pragma unroll
            for (int h = 0; h < 4; h++) {
                float4 av = sA[h * 256 + seg * 32 + s];
                if (av.x > thr[h]) S1[h] += av.y * em; else S2[h] += av.z * em;
            }
        }
    }
#pragma unroll
    for (int h = 0; h < 4; h++) {
        sS1[(h * 8 + seg) * 32 + col] = S1[h];
        sS2[(h * 8 + seg) * 32 + col] = S2[h];
    }
    __syncthreads();
    if (t < 128) {
        int h = t >> 5, c = t & 31;
        float z1 = 0.f, z2 = 0.f;
#pragma unroll
        for (int s = 0; s < 8; s++) { z1 += sS1[(h * 8 + s) * 32 + c]; z2 += sS2[(h * 8 + s) * 32 + c]; }
        g_Zp[cb][0][h * NN + j0 + c] = z1;
        g_Zp[cb][1][h * NN + j0 + c] = z2;
    }
}

// ---------------- K4: attn @ proj (4 heads), fp16 m16n8k16, cp.async double-buffer ----------------
// Grid (64 i-tiles of 64, 4 j-chunks of 1024), 256 threads. smem layout (bytes):
//   sPT [2][256 rows c][36 u32] @ 0      (projT tile double buffer; cp.async staged)
//   sW  [4][64 rows][36 u32]    @ 73728  (attention weights, fp16, stride 144B)
//   sAr [4][64] float4          @ 110592
#define SPT_OFF 0
#define SW_OFF  73728
#define SAR_OFF 110592
#define SM4_TOT 114688
__global__ void __launch_bounds__(256) k4_mma() {
    extern __shared__ char smem[];
    const uint32_t smb = smem_u32(smem);
    uint32_t* sW  = (uint32_t*)(smem + SW_OFF);
    float4*   sAr = (float4*)(smem + SAR_OFF);
    const int t = threadIdx.x;
    const int i0 = blockIdx.x * 64;
    const int jc = blockIdx.y;             // 1024 j per chunk
    const int lane = t & 31, w = t >> 5;
    const int g = lane >> 2, tg = lane & 3;
    const int mi = (w & 3) * 16, ni = (w >> 2) * 32;
    const int p = lane;     // j-pair 0..31 (w-gen)
    const int iseg = w;     // warp -> rows iseg*8..+8 (w-gen)

    sAr[t] = g_A[(t >> 6) * NN + i0 + (t & 63)];
    float acc[4][4][4];
#pragma unroll
    for (int h = 0; h < 4; h++)
#pragma unroll
        for (int n = 0; n < 4; n++)
#pragma unroll
            for (int r = 0; r < 4; r++) acc[h][n][r] = 0.f;

    // staging indices for cp.async (8 chunks of 16B per thread)
    const int sr = t >> 3, sq = t & 7;     // base row/col; rows advance by 32 per k
    const uint32_t sdst0 = smb + SPT_OFF + sr * 144 + sq * 16;
    const uint32_t* gsrc0 = g_projT + (size_t)sr * 2048 + jc * 512 + sq * 4;

    // ldmatrix lane address offsets (bytes)
    const uint32_t aA  = smb + SW_OFF + (mi + (lane & 15)) * 144 + (lane >> 4) * 16;
    const uint32_t aB0 = smb + SPT_OFF +
                         (ni + ((lane >> 4) & 1) * 8 + (lane & 7)) * 144 +
                         ((lane >> 3) & 1) * 16;
    const uint32_t* emrow = g_em + (size_t)(i0 + iseg * 8) * (NN/2) + jc * 512 + p;
    const uint4* bp4 = (const uint4*)g_Bp;

    // prologue: issue tile 0 into buffer 0
#pragma unroll
    for (int k = 0; k < 8; k++)
        cpasync16(sdst0 + k * (32 * 144), gsrc0 + (size_t)k * 32 * 2048);
    asm volatile("cp.async.commit_group;" ::: "memory");

    uint32_t emv[8];
#pragma unroll
    for (int s = 0; s < 8; s++) emv[s] = emrow[(size_t)s * (NN/2)];
    __syncthreads();

    for (int jt = 0; jt < 16; jt++) {
        const int buf = jt & 1;
        // issue next tile into the other buffer
        if (jt < 15) {
            const uint32_t nd = sdst0 + (buf ^ 1) * 36864;
            const uint32_t* ns = gsrc0 + (jt + 1) * 32;
#pragma unroll
            for (int k = 0; k < 8; k++)
                cpasync16(nd + k * (32 * 144), ns + (size_t)k * 32 * 2048);
            asm volatile("cp.async.commit_group;" ::: "memory");
        }
        // ---- w-compute into sW (fp16) ----
#pragma unroll
        for (int h = 0; h < 4; h++) {
            uint4 bp = bp4[h * 2048 + jc * 512 + jt * 32 + p];
            __nv_bfloat162 t0  = *(__nv_bfloat162*)&bp.x;
            __nv_bfloat162 t0b = *(__nv_bfloat162*)&bp.y;
            __nv_bfloat162 t1  = *(__nv_bfloat162*)&bp.z;
            __nv_bfloat162 t1b = *(__nv_bfloat162*)&bp.w;
            float thr0 = __low2float(t0), e10 = __high2float(t0), e20 = __low2float(t0b);
            float thr1 = __low2float(t1), e11 = __high2float(t1), e21 = __low2float(t1b);
#pragma unroll
            for (int s = 0; s < 8; s++) {
                float4 av = sAr[h * 64 + iseg * 8 + s];
                __nv_bfloat162 em2 = *(__nv_bfloat162*)&emv[s];
                float w0 = ((av.x > thr0) ? av.y * e10 : av.z * e20) * __low2float(em2);
                float w1 = ((av.x > thr1) ? av.y * e11 : av.z * e21) * __high2float(em2);
                sW[h * 2304 + (iseg * 8 + s) * 36 + p] = packh2(w0, w1);
            }
        }
        // prefetch em for next tile (hidden under mma phase)
        if (jt < 15) {
#pragma unroll
            for (int s = 0; s < 8; s++) emv[s] = emrow[(size_t)s * (NN/2) + (jt + 1) * 32];
        }
        // current tile's cp.async must be complete before ldmatrix
        if (jt < 15) asm volatile("cp.async.wait_group 1;" ::: "memory");
        else         asm volatile("cp.async.wait_group 0;" ::: "memory");
        __syncthreads();

        // ---- mma phase: ldmatrix fragments + m16n8k16 fp16 ----
        const uint32_t aB = aB0 + buf * 36864;
#pragma unroll
        for (int h = 0; h < 4; h++) {
            const uint32_t hA = aA + h * 9216;
            const uint32_t hB = aB + h * 9216;
#pragma unroll
            for (int kk = 0; kk < 4; kk++) {
                uint32_t a0, a1, a2, a3, b00, b01, b10, b11, b20, b21, b30, b31;
                ldsm4(a0, a1, a2, a3, hA + kk * 32);
                ldsm4(b00, b01, b10, b11, hB + kk * 32);
                ldsm4(b20, b21, b30, b31, hB + 16 * 144 + kk * 32);
                asm volatile(
                    "mma.sync.aligned.m16n8k16.row.col.f32.f16.f16.f32 "
                    "{%0,%1,%2,%3}, {%4,%5,%6,%7}, {%8,%9}, {%0,%1,%2,%3};"
                    : "+f"(acc[h][0][0]), "+f"(acc[h][0][1]), "+f"(acc[h][0][2]), "+f"(acc[h][0][3])
                    : "r"(a0), "r"(a1), "r"(a2), "r"(a3), "r"(b00), "r"(b01));
                asm volatile(
                    "mma.sync.aligned.m16n8k16.row.col.f32.f16.f16.f32 "
                    "{%0,%1,%2,%3}, {%4,%5,%6,%7}, {%8,%9}, {%0,%1,%2,%3};"
                    : "+f"(acc[h][1][0]), "+f"(acc[h][1][1]), "+f"(acc[h][1][2]), "+f"(acc[h][1][3])
                    : "r"(a0), "r"(a1), "r"(a2), "r"(a3), "r"(b10), "r"(b11));
                asm volatile(
                    "mma.sync.aligned.m16n8k16.row.col.f32.f16.f16.f32 "
                    "{%0,%1,%2,%3}, {%4,%5,%6,%7}, {%8,%9}, {%0,%1,%2,%3};"
                    : "+f"(acc[h][2][0]), "+f"(acc[h][2][1]), "+f"(acc[h][2][2]), "+f"(acc[h][2][3])
                    : "r"(a0), "r"(a1), "r"(a2), "r"(a3), "r"(b20), "r"(b21));
                asm volatile(
                    "mma.sync.aligned.m16n8k16.row.col.f32.f16.f16.f32 "
                    "{%0,%1,%2,%3}, {%4,%5,%6,%7}, {%8,%9}, {%0,%1,%2,%3};"
                    : "+f"(acc[h][3][0]), "+f"(acc[h][3][1]), "+f"(acc[h][3][2]), "+f"(acc[h][3][3])
                    : "r"(a0), "r"(a1), "r"(a2), "r"(a3), "r"(b30), "r"(b31));
            }
        }
        __syncthreads();   // all warps done reading sW before next overwrite
    }

    // ---- store partials ----
    float* pb = g_part + (size_t)jc * NN * 256;
#pragma unroll
    for (int h = 0; h < 4; h++)
#pragma unroll
        for (int nt = 0; nt < 4; nt++) {
            int col = h * 64 + ni + nt * 8 + 2 * tg;
            *(float2*)(pb + (size_t)(i0 + mi + g) * 256 + col) =
                make_float2(acc[h][nt][0], acc[h][nt][1]);
            *(float2*)(pb + (size_t)(i0 + mi + g + 8) * 256 + col) =
                make_float2(acc[h][nt][2], acc[h][nt][3]);
        }
}

// ---------------- K6: reduce partials + skip + ELU ----------------
__global__ void __launch_bounds__(256) k6_epilogue(float* __restrict__ out) {
    int gid = blockIdx.x * 256 + threadIdx.x;    // 262144 float4
    float4 s = make_float4(0.f, 0.f, 0.f, 0.f);
#pragma unroll
    for (int jc = 0; jc < 4; jc++) {
        float4 v = ((const float4*)(g_part + ((size_t)jc << 20)))[gid];
        s.x += v.x; s.y += v.y; s.z += v.z; s.w += v.w;
    }
    int i = gid >> 6, c = (gid & 63) * 4;
    float4 sk = *(const float4*)(g_hidden + (size_t)i * CC + 256 + c);
    float x0 = s.x + sk.x, x1 = s.y + sk.y, x2 = s.z + sk.z, x3 = s.w + sk.w;
    x0 = x0 > 0.f ? x0 : (__expf(x0) - 1.f);
    x1 = x1 > 0.f ? x1 : (__expf(x1) - 1.f);
    x2 = x2 > 0.f ? x2 : (__expf(x2) - 1.f);
    x3 = x3 > 0.f ? x3 : (__expf(x3) - 1.f);
    ((float4*)out)[gid] = make_float4(x0, x1, x2, x3);
}

// ---------------- launcher ----------------
extern "C" void kernel_launch(void* const* d_in, const int* in_sizes, int n_in,
                              void* d_out, int out_size) {
    const float* nodes = (const float*)d_in[0];
    const float* degm  = (const float*)d_in[1];
    // d_in[2] = edges_features_distance (unused by reference)
    const float* bond  = (const float*)d_in[3];
    const float* projp = (const float*)d_in[4];
    const float* ssrc  = (const float*)d_in[5];
    const float* stgt  = (const float*)d_in[6];
    const float* skw   = (const float*)d_in[7];
    const float* cutp  = (const float*)d_in[8];
    float* out = (float*)d_out;

    k0_weights<<<256, 256>>>(projp, skw);
    k1_gemm<<<dim3(128, 8), 256>>>(nodes);
    k1b_transpose<<<dim3(64, 4), 256>>>();
    k2_scores<<<1024, 256>>>(ssrc, stgt);
    k3_mask<<<4096, 512>>>(degm, bond, cutp, out + (size_t)NN * 256);
    k5_colsum<<<dim3(128, 4), 256>>>();
    k1d_bp<<<64, 256>>>();

    cudaFuncSetAttribute(k4_mma, cudaFuncAttributeMaxDynamicSharedMemorySize, SM4_TOT);
    k4_mma<<<dim3(64, 4), 256, SM4_TOT>>>();
    k6_epilogue<<<1024, 256>>>(out);
}